// round 1
// baseline (speedup 1.0000x reference)
#include <cuda_runtime.h>
#include <cuda_bf16.h>
#include <math.h>

// Problem constants
#define BATCH   4
#define NSEQ    2048
#define DIM     1024
#define NHEAD   16
#define HD      64          // head dim
#define M_ROWS  (BATCH * NSEQ)      // 8192
#define QKV_N   (3 * DIM)           // 3072

// ---------------------------------------------------------------------------
// Scratch (device globals: allocation-free per harness rules)
// ---------------------------------------------------------------------------
__device__ float g_qkv[M_ROWS * QKV_N];   // [8192, 3072]  q|k|v interleaved per row
__device__ float g_att[M_ROWS * DIM];     // [8192, 1024]  attention output (pre-proj)

// ---------------------------------------------------------------------------
// SGEMM: C[M,N] = A[M,K] @ B[K,N] + bias[N]
// 128x128 block tile, 8x8 per thread, BK=8, 256 threads.
// Requires M%128==0, N%128==0, K%8==0 (true for all our shapes).
// ---------------------------------------------------------------------------
#define BM 128
#define BN 128
#define BKK 8

__global__ __launch_bounds__(256, 2)
void sgemm_bias_kernel(const float* __restrict__ A,
                       const float* __restrict__ B,
                       const float* __restrict__ bias,
                       float* __restrict__ C,
                       int M, int N, int K)
{
    __shared__ float As[BKK][BM];   // transposed A tile
    __shared__ float Bs[BKK][BN];

    const int tid = threadIdx.x;
    const int bx = blockIdx.x;   // N tile
    const int by = blockIdx.y;   // M tile

    // A tile load mapping: 128 rows x 8 cols, each thread one float4
    const int arow = tid >> 1;            // 0..127
    const int acol = (tid & 1) * 4;       // 0 or 4
    // B tile load mapping: 8 rows x 128 cols, each thread one float4
    const int brow = tid >> 5;            // 0..7
    const int bcol = (tid & 31) * 4;      // 0..124

    const float* Ap = A + (size_t)(by * BM + arow) * K + acol;
    const float* Bp = B + (size_t)brow * N + bx * BN + bcol;

    // compute mapping: 16x16 thread grid of 8x8 microtiles
    const int tr = (tid >> 4) * 8;   // row offset in tile
    const int tc = (tid & 15) * 8;   // col offset in tile

    float acc[8][8];
#pragma unroll
    for (int i = 0; i < 8; i++)
#pragma unroll
        for (int j = 0; j < 8; j++) acc[i][j] = 0.f;

    for (int k0 = 0; k0 < K; k0 += BKK) {
        float4 av = *(const float4*)Ap;  Ap += BKK;
        float4 bv = *(const float4*)Bp;  Bp += (size_t)BKK * N;

        As[acol + 0][arow] = av.x;
        As[acol + 1][arow] = av.y;
        As[acol + 2][arow] = av.z;
        As[acol + 3][arow] = av.w;
        *(float4*)&Bs[brow][bcol] = bv;
        __syncthreads();

#pragma unroll
        for (int k = 0; k < BKK; k++) {
            float a[8], b[8];
            *(float4*)&a[0] = *(const float4*)&As[k][tr];
            *(float4*)&a[4] = *(const float4*)&As[k][tr + 4];
            *(float4*)&b[0] = *(const float4*)&Bs[k][tc];
            *(float4*)&b[4] = *(const float4*)&Bs[k][tc + 4];
#pragma unroll
            for (int i = 0; i < 8; i++)
#pragma unroll
                for (int j = 0; j < 8; j++)
                    acc[i][j] += a[i] * b[j];
        }
        __syncthreads();
    }

    // epilogue with bias, vectorized stores
    const int crow0 = by * BM + tr;
    const int ccol0 = bx * BN + tc;
    float4 bi0 = *(const float4*)&bias[ccol0];
    float4 bi1 = *(const float4*)&bias[ccol0 + 4];
#pragma unroll
    for (int i = 0; i < 8; i++) {
        float4 v0, v1;
        v0.x = acc[i][0] + bi0.x;  v0.y = acc[i][1] + bi0.y;
        v0.z = acc[i][2] + bi0.z;  v0.w = acc[i][3] + bi0.w;
        v1.x = acc[i][4] + bi1.x;  v1.y = acc[i][5] + bi1.y;
        v1.z = acc[i][6] + bi1.z;  v1.w = acc[i][7] + bi1.w;
        float* cp = C + (size_t)(crow0 + i) * N + ccol0;
        *(float4*)cp       = v0;
        *(float4*)(cp + 4) = v1;
    }
}

// ---------------------------------------------------------------------------
// Flash attention (fp32, online softmax).
// Grid: (NSEQ/64, NHEAD, BATCH), 256 threads (8 warps).
// Each block: 64 query rows for one (b,h). Warp w owns query rows w*8..w*8+7.
// Lane l owns keys {l, l+32} within a 64-key tile, and output cols {l, l+32}.
// smem: Qs[64][64] (unpadded, f4-broadcast reads), Ks/Vs[64][65] (padded,
// conflict-free scalar reads), Ps[64][64] (unpadded, f4-broadcast reads).
// ---------------------------------------------------------------------------
#define BQ 64
#define BKEY 64
#define KV_PAD 65
#define FLASH_SMEM_FLOATS (BQ*HD + 2*BKEY*KV_PAD + BQ*BKEY)
#define FLASH_SMEM_BYTES  (FLASH_SMEM_FLOATS * 4)

__global__ __launch_bounds__(256, 2)
void flash_attn_kernel(const float* __restrict__ qkv, float* __restrict__ out)
{
    extern __shared__ float sm[];
    float* Qs = sm;                       // [64][64]
    float* Ks = Qs + BQ * HD;             // [64][65]
    float* Vs = Ks + BKEY * KV_PAD;       // [64][65]
    float* Ps = Vs + BKEY * KV_PAD;       // [64][64]

    const int tid = threadIdx.x;
    const int w   = tid >> 5;
    const int l   = tid & 31;

    const int q0 = blockIdx.x * BQ;
    const int h  = blockIdx.y;
    const int b  = blockIdx.z;

    const float scale = 0.125f;           // 1/sqrt(64)

    // ---- load Q tile: rows q0..q0+63, cols h*64..h*64+63 of the q-part ----
    {
        const float* baseQ = qkv + ((size_t)(b * NSEQ + q0)) * QKV_N + h * HD;
        for (int i = tid; i < BQ * (HD / 4); i += 256) {
            int row = i >> 4;            // /16
            int c   = (i & 15) * 4;
            float4 v = *(const float4*)(baseQ + (size_t)row * QKV_N + c);
            *(float4*)&Qs[row * HD + c] = v;
        }
    }

    const int r0 = w * 8;                 // this warp's first query row (local)
    float m_i[8], l_i[8], o0[8], o1[8];
#pragma unroll
    for (int i = 0; i < 8; i++) {
        m_i[i] = -INFINITY; l_i[i] = 0.f; o0[i] = 0.f; o1[i] = 0.f;
    }

    const int k0 = l;        // first key this lane owns
    const int k1 = l + 32;   // second key

    for (int kt = 0; kt < NSEQ; kt += BKEY) {
        __syncthreads();     // all warps done with previous K/V (and Q loaded)

        // ---- load K,V tiles (padded rows) ----
        const float* baseK = qkv + ((size_t)(b * NSEQ + kt)) * QKV_N + DIM + h * HD;
        const float* baseV = baseK + DIM;
        for (int i = tid; i < BKEY * (HD / 4); i += 256) {
            int row = i >> 4;
            int c   = (i & 15) * 4;
            float4 kv = *(const float4*)(baseK + (size_t)row * QKV_N + c);
            float* kd = &Ks[row * KV_PAD + c];
            kd[0] = kv.x; kd[1] = kv.y; kd[2] = kv.z; kd[3] = kv.w;
            float4 vv = *(const float4*)(baseV + (size_t)row * QKV_N + c);
            float* vd = &Vs[row * KV_PAD + c];
            vd[0] = vv.x; vd[1] = vv.y; vd[2] = vv.z; vd[3] = vv.w;
        }
        __syncthreads();

        // ---- S = Q @ K^T for this warp's 8 rows, this lane's 2 keys ----
        float s0[8], s1[8];
#pragma unroll
        for (int i = 0; i < 8; i++) { s0[i] = 0.f; s1[i] = 0.f; }

#pragma unroll
        for (int d = 0; d < HD; d += 4) {
            float ka0 = Ks[k0 * KV_PAD + d + 0];
            float ka1 = Ks[k0 * KV_PAD + d + 1];
            float ka2 = Ks[k0 * KV_PAD + d + 2];
            float ka3 = Ks[k0 * KV_PAD + d + 3];
            float kb0 = Ks[k1 * KV_PAD + d + 0];
            float kb1 = Ks[k1 * KV_PAD + d + 1];
            float kb2 = Ks[k1 * KV_PAD + d + 2];
            float kb3 = Ks[k1 * KV_PAD + d + 3];
#pragma unroll
            for (int i = 0; i < 8; i++) {
                float4 q = *(const float4*)&Qs[(r0 + i) * HD + d];  // broadcast
                s0[i] += q.x * ka0; s0[i] += q.y * ka1;
                s0[i] += q.z * ka2; s0[i] += q.w * ka3;
                s1[i] += q.x * kb0; s1[i] += q.y * kb1;
                s1[i] += q.z * kb2; s1[i] += q.w * kb3;
            }
        }

        // ---- online softmax update ----
#pragma unroll
        for (int i = 0; i < 8; i++) {
            float a = s0[i] * scale;
            float c = s1[i] * scale;
            float mx = fmaxf(a, c);
#pragma unroll
            for (int off = 16; off > 0; off >>= 1)
                mx = fmaxf(mx, __shfl_xor_sync(0xffffffffu, mx, off));
            float m_new = fmaxf(m_i[i], mx);
            float corr  = __expf(m_i[i] - m_new);
            float p0 = __expf(a - m_new);
            float p1 = __expf(c - m_new);
            float ps = p0 + p1;
#pragma unroll
            for (int off = 16; off > 0; off >>= 1)
                ps += __shfl_xor_sync(0xffffffffu, ps, off);
            l_i[i] = l_i[i] * corr + ps;
            m_i[i] = m_new;
            o0[i] *= corr;
            o1[i] *= corr;
            Ps[(r0 + i) * BKEY + k0] = p0;
            Ps[(r0 + i) * BKEY + k1] = p1;
        }
        __syncwarp();

        // ---- O += P @ V : lane owns output cols {l, l+32} ----
#pragma unroll
        for (int k = 0; k < BKEY; k += 4) {
            float va0 = Vs[(k + 0) * KV_PAD + l];
            float va1 = Vs[(k + 1) * KV_PAD + l];
            float va2 = Vs[(k + 2) * KV_PAD + l];
            float va3 = Vs[(k + 3) * KV_PAD + l];
            float vb0 = Vs[(k + 0) * KV_PAD + l + 32];
            float vb1 = Vs[(k + 1) * KV_PAD + l + 32];
            float vb2 = Vs[(k + 2) * KV_PAD + l + 32];
            float vb3 = Vs[(k + 3) * KV_PAD + l + 32];
#pragma unroll
            for (int i = 0; i < 8; i++) {
                float4 p = *(const float4*)&Ps[(r0 + i) * BKEY + k];  // broadcast
                o0[i] += p.x * va0; o0[i] += p.y * va1;
                o0[i] += p.z * va2; o0[i] += p.w * va3;
                o1[i] += p.x * vb0; o1[i] += p.y * vb1;
                o1[i] += p.z * vb2; o1[i] += p.w * vb3;
            }
        }
        __syncwarp();   // Ps reuse next iteration is warp-local; K/V guarded by loop-top barrier
    }

    // ---- write normalized output: out[b*N + q0 + r0 + i][h*64 + {l, l+32}] ----
    float* ob = out + ((size_t)(b * NSEQ + q0 + r0)) * DIM + h * HD;
#pragma unroll
    for (int i = 0; i < 8; i++) {
        float inv = 1.f / l_i[i];
        ob[(size_t)i * DIM + l]      = o0[i] * inv;
        ob[(size_t)i * DIM + l + 32] = o1[i] * inv;
    }
}

// ---------------------------------------------------------------------------
// Launch
// ---------------------------------------------------------------------------
extern "C" void kernel_launch(void* const* d_in, const int* in_sizes, int n_in,
                              void* d_out, int out_size)
{
    const float* x      = (const float*)d_in[0];   // [4,2048,1024]
    const float* w_qkv  = (const float*)d_in[1];   // [1024,3072]
    const float* b_qkv  = (const float*)d_in[2];   // [3072]
    const float* w_proj = (const float*)d_in[3];   // [1024,1024]
    const float* b_proj = (const float*)d_in[4];   // [1024]
    float* out = (float*)d_out;                    // [4,2048,1024]

    float *qkv_buf, *att_buf;
    cudaGetSymbolAddress((void**)&qkv_buf, g_qkv);
    cudaGetSymbolAddress((void**)&att_buf, g_att);

    cudaFuncSetAttribute(flash_attn_kernel,
                         cudaFuncAttributeMaxDynamicSharedMemorySize,
                         FLASH_SMEM_BYTES);

    // 1) QKV projection: [8192,1024] @ [1024,3072] + bias
    {
        dim3 grid(QKV_N / BN, M_ROWS / BM);
        sgemm_bias_kernel<<<grid, 256>>>(x, w_qkv, b_qkv, qkv_buf,
                                         M_ROWS, QKV_N, DIM);
    }

    // 2) Flash attention per (b,h), 64-query tiles
    {
        dim3 grid(NSEQ / BQ, NHEAD, BATCH);
        flash_attn_kernel<<<grid, 256, FLASH_SMEM_BYTES>>>(qkv_buf, att_buf);
    }

    // 3) Output projection: [8192,1024] @ [1024,1024] + bias
    {
        dim3 grid(DIM / BN, M_ROWS / BM);
        sgemm_bias_kernel<<<grid, 256>>>(att_buf, w_proj, b_proj, out,
                                         M_ROWS, DIM, DIM);
    }
}

// round 2
// speedup vs baseline: 3.0310x; 3.0310x over previous
#include <cuda_runtime.h>
#include <cuda_bf16.h>
#include <math.h>

// Problem constants
#define BATCH   4
#define NSEQ    2048
#define DIM     1024
#define NHEAD   16
#define HD      64
#define M_ROWS  (BATCH * NSEQ)      // 8192
#define QKV_N   (3 * DIM)           // 3072

// ---------------------------------------------------------------------------
// Scratch (device globals: allocation-free per harness rules)
// ---------------------------------------------------------------------------
__device__ float g_qkv[M_ROWS * QKV_N];   // [8192, 3072]
__device__ float g_att[M_ROWS * DIM];     // [8192, 1024]

// ---------------------------------------------------------------------------
// Helpers: tf32 convert + m16n8k8 tf32 mma
// ---------------------------------------------------------------------------
__device__ __forceinline__ unsigned cvt_tf32(float f) {
    unsigned u;
    asm("cvt.rna.tf32.f32 %0, %1;" : "=r"(u) : "f"(f));
    return u;
}

__device__ __forceinline__ void mma_tf32(float* c,
                                         unsigned a0, unsigned a1, unsigned a2, unsigned a3,
                                         unsigned b0, unsigned b1) {
    asm volatile(
        "mma.sync.aligned.m16n8k8.row.col.f32.tf32.tf32.f32 "
        "{%0,%1,%2,%3},{%4,%5,%6,%7},{%8,%9},{%0,%1,%2,%3};"
        : "+f"(c[0]), "+f"(c[1]), "+f"(c[2]), "+f"(c[3])
        : "r"(a0), "r"(a1), "r"(a2), "r"(a3), "r"(b0), "r"(b1));
}

// ---------------------------------------------------------------------------
// TF32 GEMM: C[M,N] = A[M,K] @ B[K,N] + bias[N]
// 128x128x16 tile, 256 threads (8 warps, 2x4), warp tile 64x32.
// 2-stage smem pipeline. Requires M%128==0, N%128==0, K%16==0.
// ---------------------------------------------------------------------------
#define GBM 128
#define GBN 128
#define GBK 16
#define AS_STRIDE 20    // 20 mod 32 = 20 -> conflict-free frag reads
#define BS_STRIDE 136   // 136 mod 32 = 8 -> conflict-free frag reads

__global__ __launch_bounds__(256, 2)
void gemm_tf32_bias_kernel(const float* __restrict__ A,
                           const float* __restrict__ B,
                           const float* __restrict__ bias,
                           float* __restrict__ C,
                           int M, int N, int K)
{
    __shared__ unsigned As[2][GBM][AS_STRIDE];
    __shared__ unsigned Bs[2][GBK][BS_STRIDE];

    const int tid  = threadIdx.x;
    const int warp = tid >> 5;
    const int lane = tid & 31;
    const int grp  = lane >> 2;   // 0..7
    const int q4   = lane & 3;    // 0..3

    const int wm = warp >> 2;     // 0..1 : row of warp grid
    const int wn = warp & 3;      // 0..3 : col of warp grid

    const int bx = blockIdx.x;    // N tile
    const int by = blockIdx.y;    // M tile

    // Global load mapping
    // A: 128x16 -> 512 float4, thread loads idx=tid, tid+256
    const int a_row0 = tid >> 2;                 // 0..63
    const int a_col  = (tid & 3) * 4;            // 0,4,8,12
    // B: 16x128 -> 512 float4, thread loads idx=tid, tid+256
    const int b_row0 = tid >> 5;                 // 0..7
    const int b_col  = (tid & 31) * 4;           // 0..124

    const float* Ag = A + (size_t)(by * GBM) * K;
    const float* Bg = B + (size_t)bx * GBN;

    float acc[4][4][4];
#pragma unroll
    for (int mt = 0; mt < 4; mt++)
#pragma unroll
        for (int nt = 0; nt < 4; nt++)
#pragma unroll
            for (int j = 0; j < 4; j++) acc[mt][nt][j] = 0.f;

    const int NIT = K / GBK;

    // ---- preload stage 0 ----
    {
        float4 va0 = *(const float4*)(Ag + (size_t)a_row0        * K + 0 + a_col);
        float4 va1 = *(const float4*)(Ag + (size_t)(a_row0 + 64) * K + 0 + a_col);
        float4 vb0 = *(const float4*)(Bg + (size_t)(0 + b_row0)     * N + b_col);
        float4 vb1 = *(const float4*)(Bg + (size_t)(0 + b_row0 + 8) * N + b_col);
        uint4 ua0 = { cvt_tf32(va0.x), cvt_tf32(va0.y), cvt_tf32(va0.z), cvt_tf32(va0.w) };
        uint4 ua1 = { cvt_tf32(va1.x), cvt_tf32(va1.y), cvt_tf32(va1.z), cvt_tf32(va1.w) };
        uint4 ub0 = { cvt_tf32(vb0.x), cvt_tf32(vb0.y), cvt_tf32(vb0.z), cvt_tf32(vb0.w) };
        uint4 ub1 = { cvt_tf32(vb1.x), cvt_tf32(vb1.y), cvt_tf32(vb1.z), cvt_tf32(vb1.w) };
        *(uint4*)&As[0][a_row0][a_col]      = ua0;
        *(uint4*)&As[0][a_row0 + 64][a_col] = ua1;
        *(uint4*)&Bs[0][b_row0][b_col]      = ub0;
        *(uint4*)&Bs[0][b_row0 + 8][b_col]  = ub1;
    }
    __syncthreads();

    for (int it = 0; it < NIT; it++) {
        const int cur = it & 1;
        float4 va0, va1, vb0, vb1;
        const bool more = (it + 1 < NIT);
        if (more) {
            int k0 = (it + 1) * GBK;
            va0 = *(const float4*)(Ag + (size_t)a_row0        * K + k0 + a_col);
            va1 = *(const float4*)(Ag + (size_t)(a_row0 + 64) * K + k0 + a_col);
            vb0 = *(const float4*)(Bg + (size_t)(k0 + b_row0)     * N + b_col);
            vb1 = *(const float4*)(Bg + (size_t)(k0 + b_row0 + 8) * N + b_col);
        }

        // compute 2 k-chunks of 8
#pragma unroll
        for (int kk = 0; kk < 2; kk++) {
            const int kc = kk * 8;
            unsigned af[4][4];
#pragma unroll
            for (int mt = 0; mt < 4; mt++) {
                int r = wm * 64 + mt * 16 + grp;
                af[mt][0] = As[cur][r][kc + q4];
                af[mt][1] = As[cur][r + 8][kc + q4];
                af[mt][2] = As[cur][r][kc + 4 + q4];
                af[mt][3] = As[cur][r + 8][kc + 4 + q4];
            }
            unsigned bf[4][2];
#pragma unroll
            for (int nt = 0; nt < 4; nt++) {
                int cidx = wn * 32 + nt * 8 + grp;
                bf[nt][0] = Bs[cur][kc + q4][cidx];
                bf[nt][1] = Bs[cur][kc + 4 + q4][cidx];
            }
#pragma unroll
            for (int mt = 0; mt < 4; mt++)
#pragma unroll
                for (int nt = 0; nt < 4; nt++)
                    mma_tf32(acc[mt][nt], af[mt][0], af[mt][1], af[mt][2], af[mt][3],
                             bf[nt][0], bf[nt][1]);
        }

        if (more) {
            const int nxt = cur ^ 1;
            uint4 ua0 = { cvt_tf32(va0.x), cvt_tf32(va0.y), cvt_tf32(va0.z), cvt_tf32(va0.w) };
            uint4 ua1 = { cvt_tf32(va1.x), cvt_tf32(va1.y), cvt_tf32(va1.z), cvt_tf32(va1.w) };
            uint4 ub0 = { cvt_tf32(vb0.x), cvt_tf32(vb0.y), cvt_tf32(vb0.z), cvt_tf32(vb0.w) };
            uint4 ub1 = { cvt_tf32(vb1.x), cvt_tf32(vb1.y), cvt_tf32(vb1.z), cvt_tf32(vb1.w) };
            *(uint4*)&As[nxt][a_row0][a_col]      = ua0;
            *(uint4*)&As[nxt][a_row0 + 64][a_col] = ua1;
            *(uint4*)&Bs[nxt][b_row0][b_col]      = ub0;
            *(uint4*)&Bs[nxt][b_row0 + 8][b_col]  = ub1;
        }
        __syncthreads();
    }

    // ---- epilogue: add bias, write float2 pairs ----
#pragma unroll
    for (int mt = 0; mt < 4; mt++) {
        const int row = by * GBM + wm * 64 + mt * 16 + grp;
#pragma unroll
        for (int nt = 0; nt < 4; nt++) {
            const int col = bx * GBN + wn * 32 + nt * 8 + 2 * q4;
            float2 bv = *(const float2*)&bias[col];
            float2 v0 = { acc[mt][nt][0] + bv.x, acc[mt][nt][1] + bv.y };
            float2 v1 = { acc[mt][nt][2] + bv.x, acc[mt][nt][3] + bv.y };
            *(float2*)&C[(size_t)row * N + col]       = v0;
            *(float2*)&C[(size_t)(row + 8) * N + col] = v1;
        }
    }
}

// ---------------------------------------------------------------------------
// Flash attention, TF32 tensor cores.
// Grid (NSEQ/64, NHEAD, BATCH), 128 threads (4 warps).
// Warp w owns query rows w*16..w*16+15 (one m16 tile), all 64 key columns.
// smem (u32/tf32): Qs[64][68], Ks[64][68], Vs[64][72], Ps[64][68].
// ---------------------------------------------------------------------------
#define QS_STRIDE 68   // 68 mod 32 = 4  -> A/B frag pattern conflict-free
#define VS_STRIDE 72   // 72 mod 32 = 8  -> V B-frag pattern conflict-free
#define FA_SMEM_U32 (64*QS_STRIDE + 64*QS_STRIDE + 64*VS_STRIDE + 64*QS_STRIDE)
#define FA_SMEM_BYTES (FA_SMEM_U32 * 4)

__global__ __launch_bounds__(128, 2)
void flash_tf32_kernel(const float* __restrict__ qkv, float* __restrict__ out)
{
    extern __shared__ unsigned sm_u[];
    unsigned* Qs = sm_u;                       // [64][68]
    unsigned* Ks = Qs + 64 * QS_STRIDE;        // [64][68]
    unsigned* Vs = Ks + 64 * QS_STRIDE;        // [64][72]
    unsigned* Ps = Vs + 64 * VS_STRIDE;        // [64][68]

    const int tid  = threadIdx.x;
    const int w    = tid >> 5;   // 0..3
    const int lane = tid & 31;
    const int grp  = lane >> 2;  // 0..7
    const int q4   = lane & 3;   // 0..3

    const int q0 = blockIdx.x * 64;
    const int h  = blockIdx.y;
    const int b  = blockIdx.z;

    // ---- load Q tile, pre-scaled by 1/sqrt(hd)=0.125, converted to tf32 ----
    {
        const float* baseQ = qkv + (size_t)(b * NSEQ + q0) * QKV_N + h * HD;
        for (int i = tid; i < 64 * 16; i += 128) {
            int row = i >> 4;
            int c   = (i & 15) * 4;
            float4 v = *(const float4*)(baseQ + (size_t)row * QKV_N + c);
            unsigned* dst = &Qs[row * QS_STRIDE + c];
            dst[0] = cvt_tf32(v.x * 0.125f);
            dst[1] = cvt_tf32(v.y * 0.125f);
            dst[2] = cvt_tf32(v.z * 0.125f);
            dst[3] = cvt_tf32(v.w * 0.125f);
        }
    }

    float m0 = -INFINITY, m1 = -INFINITY, l0 = 0.f, l1 = 0.f;
    float o[8][4];
#pragma unroll
    for (int nt = 0; nt < 8; nt++)
#pragma unroll
        for (int j = 0; j < 4; j++) o[nt][j] = 0.f;

    const int mrow0 = w * 16 + grp;       // this thread's first S/O row (local)
    const int mrow1 = mrow0 + 8;

    for (int kt = 0; kt < NSEQ; kt += 64) {
        __syncthreads();   // previous K/V fully consumed (and Q ready on iter 0)

        // ---- load K,V tiles (tf32 converted) ----
        {
            const float* baseK = qkv + (size_t)(b * NSEQ + kt) * QKV_N + DIM + h * HD;
            const float* baseV = baseK + DIM;
            for (int i = tid; i < 64 * 16; i += 128) {
                int row = i >> 4;
                int c   = (i & 15) * 4;
                float4 kv = *(const float4*)(baseK + (size_t)row * QKV_N + c);
                unsigned* kd = &Ks[row * QS_STRIDE + c];
                kd[0] = cvt_tf32(kv.x); kd[1] = cvt_tf32(kv.y);
                kd[2] = cvt_tf32(kv.z); kd[3] = cvt_tf32(kv.w);
                float4 vv = *(const float4*)(baseV + (size_t)row * QKV_N + c);
                unsigned* vd = &Vs[row * VS_STRIDE + c];
                vd[0] = cvt_tf32(vv.x); vd[1] = cvt_tf32(vv.y);
                vd[2] = cvt_tf32(vv.z); vd[3] = cvt_tf32(vv.w);
            }
        }
        __syncthreads();

        // ---- S = Q @ K^T (scaled): 8 d-chunks, 8 n-tiles ----
        float s[8][4];
#pragma unroll
        for (int nt = 0; nt < 8; nt++)
#pragma unroll
            for (int j = 0; j < 4; j++) s[nt][j] = 0.f;

#pragma unroll
        for (int kc = 0; kc < 8; kc++) {
            const int d0 = kc * 8;
            unsigned a0 = Qs[mrow0 * QS_STRIDE + d0 + q4];
            unsigned a1 = Qs[mrow1 * QS_STRIDE + d0 + q4];
            unsigned a2 = Qs[mrow0 * QS_STRIDE + d0 + 4 + q4];
            unsigned a3 = Qs[mrow1 * QS_STRIDE + d0 + 4 + q4];
#pragma unroll
            for (int nt = 0; nt < 8; nt++) {
                unsigned b0 = Ks[(nt * 8 + grp) * QS_STRIDE + d0 + q4];
                unsigned b1 = Ks[(nt * 8 + grp) * QS_STRIDE + d0 + 4 + q4];
                mma_tf32(s[nt], a0, a1, a2, a3, b0, b1);
            }
        }

        // ---- online softmax ----
        float mx0 = -INFINITY, mx1 = -INFINITY;
#pragma unroll
        for (int nt = 0; nt < 8; nt++) {
            mx0 = fmaxf(mx0, fmaxf(s[nt][0], s[nt][1]));
            mx1 = fmaxf(mx1, fmaxf(s[nt][2], s[nt][3]));
        }
        mx0 = fmaxf(mx0, __shfl_xor_sync(0xffffffffu, mx0, 1));
        mx0 = fmaxf(mx0, __shfl_xor_sync(0xffffffffu, mx0, 2));
        mx1 = fmaxf(mx1, __shfl_xor_sync(0xffffffffu, mx1, 1));
        mx1 = fmaxf(mx1, __shfl_xor_sync(0xffffffffu, mx1, 2));

        float m0n = fmaxf(m0, mx0);
        float m1n = fmaxf(m1, mx1);
        float corr0 = __expf(m0 - m0n);
        float corr1 = __expf(m1 - m1n);

        float ps0 = 0.f, ps1 = 0.f;
#pragma unroll
        for (int nt = 0; nt < 8; nt++) {
            s[nt][0] = __expf(s[nt][0] - m0n);
            s[nt][1] = __expf(s[nt][1] - m0n);
            s[nt][2] = __expf(s[nt][2] - m1n);
            s[nt][3] = __expf(s[nt][3] - m1n);
            ps0 += s[nt][0] + s[nt][1];
            ps1 += s[nt][2] + s[nt][3];
        }
        ps0 += __shfl_xor_sync(0xffffffffu, ps0, 1);
        ps0 += __shfl_xor_sync(0xffffffffu, ps0, 2);
        ps1 += __shfl_xor_sync(0xffffffffu, ps1, 1);
        ps1 += __shfl_xor_sync(0xffffffffu, ps1, 2);

        l0 = l0 * corr0 + ps0;
        l1 = l1 * corr1 + ps1;
        m0 = m0n;  m1 = m1n;

#pragma unroll
        for (int nt = 0; nt < 8; nt++) {
            o[nt][0] *= corr0;  o[nt][1] *= corr0;
            o[nt][2] *= corr1;  o[nt][3] *= corr1;
            // store P (tf32) to warp-private smem rows
            Ps[mrow0 * QS_STRIDE + nt * 8 + 2 * q4]     = cvt_tf32(s[nt][0]);
            Ps[mrow0 * QS_STRIDE + nt * 8 + 2 * q4 + 1] = cvt_tf32(s[nt][1]);
            Ps[mrow1 * QS_STRIDE + nt * 8 + 2 * q4]     = cvt_tf32(s[nt][2]);
            Ps[mrow1 * QS_STRIDE + nt * 8 + 2 * q4 + 1] = cvt_tf32(s[nt][3]);
        }
        __syncwarp();

        // ---- O += P @ V : 8 key-chunks, 8 n-tiles ----
#pragma unroll
        for (int kc = 0; kc < 8; kc++) {
            const int k0 = kc * 8;
            unsigned a0 = Ps[mrow0 * QS_STRIDE + k0 + q4];
            unsigned a1 = Ps[mrow1 * QS_STRIDE + k0 + q4];
            unsigned a2 = Ps[mrow0 * QS_STRIDE + k0 + 4 + q4];
            unsigned a3 = Ps[mrow1 * QS_STRIDE + k0 + 4 + q4];
#pragma unroll
            for (int nt = 0; nt < 8; nt++) {
                unsigned b0 = Vs[(k0 + q4) * VS_STRIDE + nt * 8 + grp];
                unsigned b1 = Vs[(k0 + 4 + q4) * VS_STRIDE + nt * 8 + grp];
                mma_tf32(o[nt], a0, a1, a2, a3, b0, b1);
            }
        }
        __syncwarp();
    }

    // ---- normalize + write ----
    const float inv0 = 1.f / l0;
    const float inv1 = 1.f / l1;
    float* ob = out + (size_t)(b * NSEQ + q0 + mrow0) * DIM + h * HD;
    float* ob1 = ob + (size_t)8 * DIM;
#pragma unroll
    for (int nt = 0; nt < 8; nt++) {
        const int col = nt * 8 + 2 * q4;
        float2 v0 = { o[nt][0] * inv0, o[nt][1] * inv0 };
        float2 v1 = { o[nt][2] * inv1, o[nt][3] * inv1 };
        *(float2*)&ob[col]  = v0;
        *(float2*)&ob1[col] = v1;
    }
}

// ---------------------------------------------------------------------------
// Launch
// ---------------------------------------------------------------------------
extern "C" void kernel_launch(void* const* d_in, const int* in_sizes, int n_in,
                              void* d_out, int out_size)
{
    const float* x      = (const float*)d_in[0];   // [4,2048,1024]
    const float* w_qkv  = (const float*)d_in[1];   // [1024,3072]
    const float* b_qkv  = (const float*)d_in[2];   // [3072]
    const float* w_proj = (const float*)d_in[3];   // [1024,1024]
    const float* b_proj = (const float*)d_in[4];   // [1024]
    float* out = (float*)d_out;                    // [4,2048,1024]

    float *qkv_buf, *att_buf;
    cudaGetSymbolAddress((void**)&qkv_buf, g_qkv);
    cudaGetSymbolAddress((void**)&att_buf, g_att);

    cudaFuncSetAttribute(flash_tf32_kernel,
                         cudaFuncAttributeMaxDynamicSharedMemorySize,
                         FA_SMEM_BYTES);

    // 1) QKV projection: [8192,1024] @ [1024,3072] + bias
    {
        dim3 grid(QKV_N / GBN, M_ROWS / GBM);
        gemm_tf32_bias_kernel<<<grid, 256>>>(x, w_qkv, b_qkv, qkv_buf,
                                             M_ROWS, QKV_N, DIM);
    }

    // 2) Flash attention per (b,h), 64-query tiles
    {
        dim3 grid(NSEQ / 64, NHEAD, BATCH);
        flash_tf32_kernel<<<grid, 128, FA_SMEM_BYTES>>>(qkv_buf, att_buf);
    }

    // 3) Output projection: [8192,1024] @ [1024,1024] + bias
    {
        dim3 grid(DIM / GBN, M_ROWS / GBM);
        gemm_tf32_bias_kernel<<<grid, 256>>>(att_buf, w_proj, b_proj, out,
                                             M_ROWS, DIM, DIM);
    }
}

// round 5
// speedup vs baseline: 5.3201x; 1.7553x over previous
#include <cuda_runtime.h>
#include <cuda_fp16.h>
#include <math.h>
#include <stdint.h>

// Problem constants
#define BATCH   4
#define NSEQ    2048
#define DIM     1024
#define NHEAD   16
#define HD      64
#define M_ROWS  (BATCH * NSEQ)      // 8192
#define QKV_N   (3 * DIM)           // 3072

// ---------------------------------------------------------------------------
// Scratch (device globals: allocation-free per harness rules)
// ---------------------------------------------------------------------------
__device__ __half g_x_h[M_ROWS * DIM];       // x in fp16
__device__ __half g_qkv_h[M_ROWS * QKV_N];   // qkv in fp16
__device__ __half g_att_h[M_ROWS * DIM];     // attention out in fp16
__device__ __half g_wqkv_h[QKV_N * DIM];     // W_qkv^T  [3072,1024] fp16
__device__ __half g_wproj_h[DIM * DIM];      // W_proj^T [1024,1024] fp16

// ---------------------------------------------------------------------------
// Helpers
// ---------------------------------------------------------------------------
__device__ __forceinline__ uint32_t smem_u32(const void* p) {
    uint32_t a;
    asm("{ .reg .u64 t; cvta.to.shared.u64 t, %1; cvt.u32.u64 %0, t; }"
        : "=r"(a) : "l"(p));
    return a;
}

__device__ __forceinline__ void cp_async16(uint32_t dst, const void* src) {
    asm volatile("cp.async.cg.shared.global [%0], [%1], 16;" :: "r"(dst), "l"(src));
}
__device__ __forceinline__ void cp_commit() {
    asm volatile("cp.async.commit_group;" ::: "memory");
}
__device__ __forceinline__ void cp_wait1() {
    asm volatile("cp.async.wait_group 1;" ::: "memory");
}

__device__ __forceinline__ void ldsm_x4(unsigned* r, uint32_t addr) {
    asm volatile("ldmatrix.sync.aligned.m8n8.x4.shared.b16 {%0,%1,%2,%3}, [%4];"
                 : "=r"(r[0]), "=r"(r[1]), "=r"(r[2]), "=r"(r[3]) : "r"(addr));
}

// mma m16n8k16 fp16 -> fp32
__device__ __forceinline__ void mma_f16(float* c,
                                        unsigned a0, unsigned a1, unsigned a2, unsigned a3,
                                        unsigned b0, unsigned b1) {
    asm volatile(
        "mma.sync.aligned.m16n8k16.row.col.f32.f16.f16.f32 "
        "{%0,%1,%2,%3},{%4,%5,%6,%7},{%8,%9},{%0,%1,%2,%3};"
        : "+f"(c[0]), "+f"(c[1]), "+f"(c[2]), "+f"(c[3])
        : "r"(a0), "r"(a1), "r"(a2), "r"(a3), "r"(b0), "r"(b1));
}

// ---------------------------------------------------------------------------
// f32 -> f16 convert
// ---------------------------------------------------------------------------
__global__ void f32_to_f16_kernel(const float* __restrict__ in, __half* __restrict__ outp, int n)
{
    int i = (blockIdx.x * blockDim.x + threadIdx.x) * 4;
    if (i < n) {
        float4 v = *(const float4*)(in + i);
        *(__half2*)(outp + i)     = __floats2half2_rn(v.x, v.y);
        *(__half2*)(outp + i + 2) = __floats2half2_rn(v.z, v.w);
    }
}

// ---------------------------------------------------------------------------
// Transpose + convert: out_h[c][r] = (half) in[r][c]
// ---------------------------------------------------------------------------
__global__ void transpose_cvt_kernel(const float* __restrict__ in, __half* __restrict__ outp,
                                     int R, int C)
{
    __shared__ float t[32][33];
    const int c0 = blockIdx.x * 32;
    const int r0 = blockIdx.y * 32;
    for (int i = threadIdx.y; i < 32; i += 8)
        t[i][threadIdx.x] = in[(size_t)(r0 + i) * C + c0 + threadIdx.x];
    __syncthreads();
    for (int i = threadIdx.y; i < 32; i += 8)
        outp[(size_t)(c0 + i) * R + r0 + threadIdx.x] = __float2half(t[threadIdx.x][i]);
}

// ---------------------------------------------------------------------------
// HGEMM: C[M,N] = A[M,K] @ Bt^T + bias   (A [M,K] half, Bt [N,K] half, K-major)
// 128x128 tile, BK=32 halves (64 B/row), 256 threads (8 warps 2x4),
// warp tile 64x32, 3-stage cp.async pipeline, ldmatrix fragment loads.
// smem rows swizzled: 16B-chunk c stored at c ^ ((row>>1)&3).
// ---------------------------------------------------------------------------
#define TS 3
#define OPB 8192                      // one operand tile: 128 rows * 64 B
#define STAGEB (2 * OPB)
#define GEMM_SMEM (TS * STAGEB)       // 49152

template <bool OUT_HALF>
__global__ __launch_bounds__(256, 2)
void hgemm_kernel(const __half* __restrict__ A,
                  const __half* __restrict__ Bt,
                  const float* __restrict__ bias,
                  void* __restrict__ Cv,
                  int M, int N, int K)
{
    extern __shared__ __align__(16) unsigned char dsm[];
    const uint32_t smem_base = smem_u32(dsm);

    const int tid  = threadIdx.x;
    const int warp = tid >> 5;
    const int lane = tid & 31;
    const int grp  = lane >> 2;
    const int q4   = lane & 3;

    const int wm = warp >> 2;       // 0..1
    const int wn = warp & 3;        // 0..3
    const int bx = blockIdx.x;      // N tile
    const int by = blockIdx.y;      // M tile

    const __half* Ag = A  + (size_t)(by * 128) * K;
    const __half* Bg = Bt + (size_t)(bx * 128) * K;
    const int NK = K / 32;

    // loader chunk mapping: chunk ch in 0..511 per operand: r=ch>>2, c=ch&3
    const int r_l = tid >> 2;       // row for chunk tid (and +64 for chunk tid+256)
    const int c_l = tid & 3;

    // ldmatrix address bases
    const int rowA_base = wm * 64 + (lane & 15);
    const int selA = (rowA_base >> 1) & 3;
    const int hiA  = lane >> 4;                                 // 0/1
    const int rowB_base = wn * 32 + (lane & 7) + ((lane & 16) ? 8 : 0);
    const int selB = (rowB_base >> 1) & 3;
    const int hiB  = (lane >> 3) & 1;

    float acc[4][4][4];
#pragma unroll
    for (int mt = 0; mt < 4; mt++)
#pragma unroll
        for (int nt = 0; nt < 4; nt++)
#pragma unroll
            for (int j = 0; j < 4; j++) acc[mt][nt][j] = 0.f;

    // ---- load a stage: tile index -> slot s ----
    auto load_stage = [&](int tile, int s) {
        const uint32_t base = smem_base + (uint32_t)s * STAGEB;
        const int koff = tile * 32;
#pragma unroll
        for (int j = 0; j < 2; j++) {
            const int r = r_l + j * 64;
            const uint32_t dst = base + 64u * r + 16u * (uint32_t)(c_l ^ ((r >> 1) & 3));
            cp_async16(dst,       Ag + (size_t)r * K + koff + c_l * 8);
            cp_async16(dst + OPB, Bg + (size_t)r * K + koff + c_l * 8);
        }
        cp_commit();
    };

    // prime 2 tiles
    load_stage(0, 0);
    load_stage(1, 1);

    for (int it = 0; it < NK; it++) {
        cp_wait1();            // tile `it` resident
        __syncthreads();       // publish + all warps done with tile it-1's slot

        // prefetch tile it+2 into the slot tile it-1 used
        if (it + 2 < NK) load_stage(it + 2, (it + 2) % TS);
        else             cp_commit();   // keep group count consistent

        const uint32_t sA = smem_base + (uint32_t)(it % TS) * STAGEB;
        const uint32_t sB = sA + OPB;

#pragma unroll
        for (int kk = 0; kk < 2; kk++) {
            const int c0 = kk * 2;
            unsigned af[4][4];
#pragma unroll
            for (int mt = 0; mt < 4; mt++)
                ldsm_x4(af[mt], sA + 64u * (rowA_base + mt * 16)
                                   + 16u * (uint32_t)((c0 + hiA) ^ selA));
            unsigned bf[2][4];
#pragma unroll
            for (int ntp = 0; ntp < 2; ntp++)
                ldsm_x4(bf[ntp], sB + 64u * (rowB_base + ntp * 16)
                                    + 16u * (uint32_t)((c0 + hiB) ^ selB));
#pragma unroll
            for (int mt = 0; mt < 4; mt++)
#pragma unroll
                for (int nt = 0; nt < 4; nt++)
                    mma_f16(acc[mt][nt],
                            af[mt][0], af[mt][1], af[mt][2], af[mt][3],
                            bf[nt >> 1][(nt & 1) * 2], bf[nt >> 1][(nt & 1) * 2 + 1]);
        }
    }

    // ---- epilogue ----
#pragma unroll
    for (int mt = 0; mt < 4; mt++) {
        const int row = by * 128 + wm * 64 + mt * 16 + grp;
#pragma unroll
        for (int nt = 0; nt < 4; nt++) {
            const int col = bx * 128 + wn * 32 + nt * 8 + 2 * q4;
            float2 bv = *(const float2*)&bias[col];
            float v0 = acc[mt][nt][0] + bv.x;
            float v1 = acc[mt][nt][1] + bv.y;
            float v2 = acc[mt][nt][2] + bv.x;
            float v3 = acc[mt][nt][3] + bv.y;
            if (OUT_HALF) {
                __half* C = (__half*)Cv;
                *(__half2*)&C[(size_t)row * N + col]       = __floats2half2_rn(v0, v1);
                *(__half2*)&C[(size_t)(row + 8) * N + col] = __floats2half2_rn(v2, v3);
            } else {
                float* C = (float*)Cv;
                float2 w0 = { v0, v1 }, w1 = { v2, v3 };
                *(float2*)&C[(size_t)row * N + col]       = w0;
                *(float2*)&C[(size_t)(row + 8) * N + col] = w1;
            }
        }
    }
}

// ---------------------------------------------------------------------------
// Flash attention, fp16 mma m16n8k16, online softmax.
// Grid (NSEQ/64, NHEAD, BATCH), 128 threads (4 warps).
// Warp w owns query rows w*16..w*16+15. Per tile: 64 keys.
// smem word layouts (unsigned = half2):
//   Qs[64][36] : Q row-major, word = halves (2d, 2d+1), pre-scaled by 0.125
//   Ks[64][36] : K row-major (keys x d-pairs)
//   Vp[32][68] : key-pair-packed V: word(pr, d) = {V[2pr][d], V[2pr+1][d]}
//   Ps[64][36] : P row-major (queries x key-pairs)
// ---------------------------------------------------------------------------
#define QW 36
#define VS 68
#define PW 36

__global__ __launch_bounds__(128, 4)
void flash_f16_kernel(const __half* __restrict__ qkv, __half* __restrict__ outp)
{
    __shared__ unsigned Qs[64 * QW];
    __shared__ unsigned Ks[64 * QW];
    __shared__ unsigned Vp[32 * VS];
    __shared__ unsigned Ps[64 * PW];

    const int tid  = threadIdx.x;
    const int w    = tid >> 5;
    const int lane = tid & 31;
    const int grp  = lane >> 2;
    const int q4   = lane & 3;

    const int q0 = blockIdx.x * 64;
    const int h  = blockIdx.y;
    const int b  = blockIdx.z;

    // ---- load Q tile (scaled by 1/8, exact in fp16) ----
    {
        const __half* baseQ = qkv + (size_t)(b * NSEQ + q0) * QKV_N + h * HD;
        const __half2 qs = __floats2half2_rn(0.125f, 0.125f);
        for (int i = tid; i < 512; i += 128) {
            const int row = i >> 3;
            const int c   = i & 7;
            uint4 v = *(const uint4*)(baseQ + (size_t)row * QKV_N + c * 8);
            __half2 h0 = __hmul2(*(__half2*)&v.x, qs);
            __half2 h1 = __hmul2(*(__half2*)&v.y, qs);
            __half2 h2 = __hmul2(*(__half2*)&v.z, qs);
            __half2 h3 = __hmul2(*(__half2*)&v.w, qs);
            unsigned* dst = &Qs[row * QW + c * 4];
            dst[0] = *(unsigned*)&h0; dst[1] = *(unsigned*)&h1;
            dst[2] = *(unsigned*)&h2; dst[3] = *(unsigned*)&h3;
        }
    }

    float m0 = -INFINITY, m1 = -INFINITY, l0 = 0.f, l1 = 0.f;
    float o[8][4];
#pragma unroll
    for (int nt = 0; nt < 8; nt++)
#pragma unroll
        for (int j = 0; j < 4; j++) o[nt][j] = 0.f;

    const int mrow0 = w * 16 + grp;
    const int mrow1 = mrow0 + 8;

    for (int kt = 0; kt < NSEQ; kt += 64) {
        __syncthreads();   // previous K/V fully consumed

        // ---- load K tile ----
        {
            const __half* baseK = qkv + (size_t)(b * NSEQ + kt) * QKV_N + DIM + h * HD;
            for (int i = tid; i < 512; i += 128) {
                const int row = i >> 3;
                const int c   = i & 7;
                uint4 v = *(const uint4*)(baseK + (size_t)row * QKV_N + c * 8);
                *(uint4*)&Ks[row * QW + c * 4] = v;
            }
        }
        // ---- load V tile, key-pair packed ----
        {
            const __half* baseV = qkv + (size_t)(b * NSEQ + kt) * QKV_N + 2 * DIM + h * HD;
            for (int i = tid; i < 256; i += 128) {
                const int pr = i >> 3;    // key pair 0..31
                const int dc = i & 7;     // d-chunk of 8
                uint4 A = *(const uint4*)(baseV + (size_t)(2 * pr)     * QKV_N + dc * 8);
                uint4 B = *(const uint4*)(baseV + (size_t)(2 * pr + 1) * QKV_N + dc * 8);
                unsigned* dst = &Vp[pr * VS + dc * 8];
                dst[0] = __byte_perm(A.x, B.x, 0x5410);
                dst[1] = __byte_perm(A.x, B.x, 0x7632);
                dst[2] = __byte_perm(A.y, B.y, 0x5410);
                dst[3] = __byte_perm(A.y, B.y, 0x7632);
                dst[4] = __byte_perm(A.z, B.z, 0x5410);
                dst[5] = __byte_perm(A.z, B.z, 0x7632);
                dst[6] = __byte_perm(A.w, B.w, 0x5410);
                dst[7] = __byte_perm(A.w, B.w, 0x7632);
            }
        }
        __syncthreads();

        // ---- S = Qs @ K^T : 4 k16 chunks x 8 n-tiles ----
        float s[8][4];
#pragma unroll
        for (int nt = 0; nt < 8; nt++)
#pragma unroll
            for (int j = 0; j < 4; j++) s[nt][j] = 0.f;

#pragma unroll
        for (int kc = 0; kc < 4; kc++) {
            const int w0 = kc * 8;
            unsigned a0 = Qs[mrow0 * QW + w0 + q4];
            unsigned a1 = Qs[mrow1 * QW + w0 + q4];
            unsigned a2 = Qs[mrow0 * QW + w0 + 4 + q4];
            unsigned a3 = Qs[mrow1 * QW + w0 + 4 + q4];
#pragma unroll
            for (int nt = 0; nt < 8; nt++) {
                unsigned b0 = Ks[(nt * 8 + grp) * QW + w0 + q4];
                unsigned b1 = Ks[(nt * 8 + grp) * QW + w0 + 4 + q4];
                mma_f16(s[nt], a0, a1, a2, a3, b0, b1);
            }
        }

        // ---- online softmax ----
        float mx0 = -INFINITY, mx1 = -INFINITY;
#pragma unroll
        for (int nt = 0; nt < 8; nt++) {
            mx0 = fmaxf(mx0, fmaxf(s[nt][0], s[nt][1]));
            mx1 = fmaxf(mx1, fmaxf(s[nt][2], s[nt][3]));
        }
        mx0 = fmaxf(mx0, __shfl_xor_sync(0xffffffffu, mx0, 1));
        mx0 = fmaxf(mx0, __shfl_xor_sync(0xffffffffu, mx0, 2));
        mx1 = fmaxf(mx1, __shfl_xor_sync(0xffffffffu, mx1, 1));
        mx1 = fmaxf(mx1, __shfl_xor_sync(0xffffffffu, mx1, 2));

        const float m0n = fmaxf(m0, mx0);
        const float m1n = fmaxf(m1, mx1);
        const float corr0 = __expf(m0 - m0n);
        const float corr1 = __expf(m1 - m1n);

        float ps0 = 0.f, ps1 = 0.f;
#pragma unroll
        for (int nt = 0; nt < 8; nt++) {
            s[nt][0] = __expf(s[nt][0] - m0n);
            s[nt][1] = __expf(s[nt][1] - m0n);
            s[nt][2] = __expf(s[nt][2] - m1n);
            s[nt][3] = __expf(s[nt][3] - m1n);
            ps0 += s[nt][0] + s[nt][1];
            ps1 += s[nt][2] + s[nt][3];
        }
        ps0 += __shfl_xor_sync(0xffffffffu, ps0, 1);
        ps0 += __shfl_xor_sync(0xffffffffu, ps0, 2);
        ps1 += __shfl_xor_sync(0xffffffffu, ps1, 1);
        ps1 += __shfl_xor_sync(0xffffffffu, ps1, 2);

        l0 = l0 * corr0 + ps0;
        l1 = l1 * corr1 + ps1;
        m0 = m0n;  m1 = m1n;

#pragma unroll
        for (int nt = 0; nt < 8; nt++) {
            o[nt][0] *= corr0;  o[nt][1] *= corr0;
            o[nt][2] *= corr1;  o[nt][3] *= corr1;
            __half2 p0 = __floats2half2_rn(s[nt][0], s[nt][1]);
            __half2 p1 = __floats2half2_rn(s[nt][2], s[nt][3]);
            Ps[mrow0 * PW + nt * 4 + q4] = *(unsigned*)&p0;
            Ps[mrow1 * PW + nt * 4 + q4] = *(unsigned*)&p1;
        }
        __syncwarp();

        // ---- O += P @ V : 4 k16 chunks x 8 n-tiles ----
#pragma unroll
        for (int kc = 0; kc < 4; kc++) {
            const int w0 = kc * 8;
            unsigned a0 = Ps[mrow0 * PW + w0 + q4];
            unsigned a1 = Ps[mrow1 * PW + w0 + q4];
            unsigned a2 = Ps[mrow0 * PW + w0 + 4 + q4];
            unsigned a3 = Ps[mrow1 * PW + w0 + 4 + q4];
#pragma unroll
            for (int nt = 0; nt < 8; nt++) {
                unsigned b0 = Vp[(w0 + q4) * VS + nt * 8 + grp];
                unsigned b1 = Vp[(w0 + 4 + q4) * VS + nt * 8 + grp];
                mma_f16(o[nt], a0, a1, a2, a3, b0, b1);
            }
        }
        __syncwarp();   // warp-local Ps reuse; K/V guarded by loop-top barrier
    }

    // ---- normalize + write (fp16) ----
    const float inv0 = 1.f / l0;
    const float inv1 = 1.f / l1;
    __half* ob  = outp + (size_t)(b * NSEQ + q0 + mrow0) * DIM + h * HD;
    __half* ob1 = ob + (size_t)8 * DIM;
#pragma unroll
    for (int nt = 0; nt < 8; nt++) {
        const int col = nt * 8 + 2 * q4;
        __half2 v0 = __floats2half2_rn(o[nt][0] * inv0, o[nt][1] * inv0);
        __half2 v1 = __floats2half2_rn(o[nt][2] * inv1, o[nt][3] * inv1);
        *(__half2*)&ob[col]  = v0;
        *(__half2*)&ob1[col] = v1;
    }
}

// ---------------------------------------------------------------------------
// Launch
// ---------------------------------------------------------------------------
extern "C" void kernel_launch(void* const* d_in, const int* in_sizes, int n_in,
                              void* d_out, int out_size)
{
    const float* x      = (const float*)d_in[0];   // [4,2048,1024]
    const float* w_qkv  = (const float*)d_in[1];   // [1024,3072]
    const float* b_qkv  = (const float*)d_in[2];   // [3072]
    const float* w_proj = (const float*)d_in[3];   // [1024,1024]
    const float* b_proj = (const float*)d_in[4];   // [1024]
    float* out = (float*)d_out;                    // [4,2048,1024]

    __half *x_h, *qkv_h, *att_h, *wqkv_h, *wproj_h;
    cudaGetSymbolAddress((void**)&x_h,     g_x_h);
    cudaGetSymbolAddress((void**)&qkv_h,   g_qkv_h);
    cudaGetSymbolAddress((void**)&att_h,   g_att_h);
    cudaGetSymbolAddress((void**)&wqkv_h,  g_wqkv_h);
    cudaGetSymbolAddress((void**)&wproj_h, g_wproj_h);

    cudaFuncSetAttribute(hgemm_kernel<true>,
                         cudaFuncAttributeMaxDynamicSharedMemorySize, GEMM_SMEM);
    cudaFuncSetAttribute(hgemm_kernel<false>,
                         cudaFuncAttributeMaxDynamicSharedMemorySize, GEMM_SMEM);

    // 0) precision converts + weight transposes
    {
        int n = M_ROWS * DIM;
        f32_to_f16_kernel<<<(n / 4 + 255) / 256, 256>>>(x, x_h, n);
        dim3 blk(32, 8);
        transpose_cvt_kernel<<<dim3(QKV_N / 32, DIM / 32), blk>>>(w_qkv, wqkv_h, DIM, QKV_N);
        transpose_cvt_kernel<<<dim3(DIM / 32, DIM / 32), blk>>>(w_proj, wproj_h, DIM, DIM);
    }

    // 1) QKV projection: [8192,1024] @ [1024,3072] + bias -> fp16
    {
        dim3 grid(QKV_N / 128, M_ROWS / 128);
        hgemm_kernel<true><<<grid, 256, GEMM_SMEM>>>(x_h, wqkv_h, b_qkv, qkv_h,
                                                     M_ROWS, QKV_N, DIM);
    }

    // 2) Flash attention per (b,h), 64-query tiles
    {
        dim3 grid(NSEQ / 64, NHEAD, BATCH);
        flash_f16_kernel<<<grid, 128>>>(qkv_h, att_h);
    }

    // 3) Output projection: [8192,1024] @ [1024,1024] + bias -> fp32
    {
        dim3 grid(DIM / 128, M_ROWS / 128);
        hgemm_kernel<false><<<grid, 256, GEMM_SMEM>>>(att_h, wproj_h, b_proj, out,
                                                      M_ROWS, DIM, DIM);
    }
}

// round 6
// speedup vs baseline: 8.0462x; 1.5124x over previous
#include <cuda_runtime.h>
#include <cuda_fp16.h>
#include <math.h>
#include <stdint.h>

// Problem constants
#define BATCH   4
#define NSEQ    2048
#define DIM     1024
#define NHEAD   16
#define HD      64
#define M_ROWS  (BATCH * NSEQ)      // 8192
#define QKV_N   (3 * DIM)           // 3072

// ---------------------------------------------------------------------------
// Scratch (device globals: allocation-free per harness rules)
// ---------------------------------------------------------------------------
__device__ __half g_x_h[M_ROWS * DIM];       // x in fp16
__device__ __half g_qkv_h[M_ROWS * QKV_N];   // qkv in fp16
__device__ __half g_att_h[M_ROWS * DIM];     // attention out in fp16
__device__ __half g_wqkv_h[QKV_N * DIM];     // W_qkv^T  [3072,1024] fp16
__device__ __half g_wproj_h[DIM * DIM];      // W_proj^T [1024,1024] fp16

// ---------------------------------------------------------------------------
// Helpers
// ---------------------------------------------------------------------------
__device__ __forceinline__ uint32_t smem_u32(const void* p) {
    uint32_t a;
    asm("{ .reg .u64 t; cvta.to.shared.u64 t, %1; cvt.u32.u64 %0, t; }"
        : "=r"(a) : "l"(p));
    return a;
}

__device__ __forceinline__ void cp_async16(uint32_t dst, const void* src) {
    asm volatile("cp.async.cg.shared.global [%0], [%1], 16;" :: "r"(dst), "l"(src));
}
__device__ __forceinline__ void cp_commit() {
    asm volatile("cp.async.commit_group;" ::: "memory");
}
__device__ __forceinline__ void cp_wait0() {
    asm volatile("cp.async.wait_group 0;" ::: "memory");
}
__device__ __forceinline__ void cp_wait1() {
    asm volatile("cp.async.wait_group 1;" ::: "memory");
}

__device__ __forceinline__ void ldsm_x4(unsigned* r, uint32_t addr) {
    asm volatile("ldmatrix.sync.aligned.m8n8.x4.shared.b16 {%0,%1,%2,%3}, [%4];"
                 : "=r"(r[0]), "=r"(r[1]), "=r"(r[2]), "=r"(r[3]) : "r"(addr));
}
__device__ __forceinline__ void ldsm_x4_t(unsigned* r, uint32_t addr) {
    asm volatile("ldmatrix.sync.aligned.m8n8.x4.trans.shared.b16 {%0,%1,%2,%3}, [%4];"
                 : "=r"(r[0]), "=r"(r[1]), "=r"(r[2]), "=r"(r[3]) : "r"(addr));
}

// mma m16n8k16 fp16 -> fp32
__device__ __forceinline__ void mma_f16(float* c,
                                        unsigned a0, unsigned a1, unsigned a2, unsigned a3,
                                        unsigned b0, unsigned b1) {
    asm volatile(
        "mma.sync.aligned.m16n8k16.row.col.f32.f16.f16.f32 "
        "{%0,%1,%2,%3},{%4,%5,%6,%7},{%8,%9},{%0,%1,%2,%3};"
        : "+f"(c[0]), "+f"(c[1]), "+f"(c[2]), "+f"(c[3])
        : "r"(a0), "r"(a1), "r"(a2), "r"(a3), "r"(b0), "r"(b1));
}

// pack (lo, hi) f32 -> f16x2, then 2^x elementwise
__device__ __forceinline__ unsigned ex2_f16x2(float lo, float hi) {
    unsigned r;
    asm("{ .reg .b32 t; cvt.rn.f16x2.f32 t, %2, %1; ex2.approx.f16x2 %0, t; }"
        : "=r"(r) : "f"(lo), "f"(hi));
    return r;
}

// ---------------------------------------------------------------------------
// f32 -> f16 convert
// ---------------------------------------------------------------------------
__global__ void f32_to_f16_kernel(const float* __restrict__ in, __half* __restrict__ outp, int n)
{
    int i = (blockIdx.x * blockDim.x + threadIdx.x) * 4;
    if (i < n) {
        float4 v = *(const float4*)(in + i);
        *(__half2*)(outp + i)     = __floats2half2_rn(v.x, v.y);
        *(__half2*)(outp + i + 2) = __floats2half2_rn(v.z, v.w);
    }
}

// ---------------------------------------------------------------------------
// Transpose + convert: out_h[c][r] = (half) in[r][c]
// ---------------------------------------------------------------------------
__global__ void transpose_cvt_kernel(const float* __restrict__ in, __half* __restrict__ outp,
                                     int R, int C)
{
    __shared__ float t[32][33];
    const int c0 = blockIdx.x * 32;
    const int r0 = blockIdx.y * 32;
    for (int i = threadIdx.y; i < 32; i += 8)
        t[i][threadIdx.x] = in[(size_t)(r0 + i) * C + c0 + threadIdx.x];
    __syncthreads();
    for (int i = threadIdx.y; i < 32; i += 8)
        outp[(size_t)(c0 + i) * R + r0 + threadIdx.x] = __float2half(t[threadIdx.x][i]);
}

// ---------------------------------------------------------------------------
// HGEMM (unchanged from R4): C[M,N] = A[M,K] @ Bt^T + bias
// ---------------------------------------------------------------------------
#define TS 3
#define OPB 8192
#define STAGEB (2 * OPB)
#define GEMM_SMEM (TS * STAGEB)

template <bool OUT_HALF>
__global__ __launch_bounds__(256, 2)
void hgemm_kernel(const __half* __restrict__ A,
                  const __half* __restrict__ Bt,
                  const float* __restrict__ bias,
                  void* __restrict__ Cv,
                  int M, int N, int K)
{
    extern __shared__ __align__(16) unsigned char dsm[];
    const uint32_t smem_base = smem_u32(dsm);

    const int tid  = threadIdx.x;
    const int warp = tid >> 5;
    const int lane = tid & 31;
    const int grp  = lane >> 2;
    const int q4   = lane & 3;

    const int wm = warp >> 2;
    const int wn = warp & 3;
    const int bx = blockIdx.x;
    const int by = blockIdx.y;

    const __half* Ag = A  + (size_t)(by * 128) * K;
    const __half* Bg = Bt + (size_t)(bx * 128) * K;
    const int NK = K / 32;

    const int r_l = tid >> 2;
    const int c_l = tid & 3;

    const int rowA_base = wm * 64 + (lane & 15);
    const int selA = (rowA_base >> 1) & 3;
    const int hiA  = lane >> 4;
    const int rowB_base = wn * 32 + (lane & 7) + ((lane & 16) ? 8 : 0);
    const int selB = (rowB_base >> 1) & 3;
    const int hiB  = (lane >> 3) & 1;

    float acc[4][4][4];
#pragma unroll
    for (int mt = 0; mt < 4; mt++)
#pragma unroll
        for (int nt = 0; nt < 4; nt++)
#pragma unroll
            for (int j = 0; j < 4; j++) acc[mt][nt][j] = 0.f;

    auto load_stage = [&](int tile, int s) {
        const uint32_t base = smem_base + (uint32_t)s * STAGEB;
        const int koff = tile * 32;
#pragma unroll
        for (int j = 0; j < 2; j++) {
            const int r = r_l + j * 64;
            const uint32_t dst = base + 64u * r + 16u * (uint32_t)(c_l ^ ((r >> 1) & 3));
            cp_async16(dst,       Ag + (size_t)r * K + koff + c_l * 8);
            cp_async16(dst + OPB, Bg + (size_t)r * K + koff + c_l * 8);
        }
        cp_commit();
    };

    load_stage(0, 0);
    load_stage(1, 1);

    for (int it = 0; it < NK; it++) {
        cp_wait1();
        __syncthreads();

        if (it + 2 < NK) load_stage(it + 2, (it + 2) % TS);
        else             cp_commit();

        const uint32_t sA = smem_base + (uint32_t)(it % TS) * STAGEB;
        const uint32_t sB = sA + OPB;

#pragma unroll
        for (int kk = 0; kk < 2; kk++) {
            const int c0 = kk * 2;
            unsigned af[4][4];
#pragma unroll
            for (int mt = 0; mt < 4; mt++)
                ldsm_x4(af[mt], sA + 64u * (rowA_base + mt * 16)
                                   + 16u * (uint32_t)((c0 + hiA) ^ selA));
            unsigned bf[2][4];
#pragma unroll
            for (int ntp = 0; ntp < 2; ntp++)
                ldsm_x4(bf[ntp], sB + 64u * (rowB_base + ntp * 16)
                                    + 16u * (uint32_t)((c0 + hiB) ^ selB));
#pragma unroll
            for (int mt = 0; mt < 4; mt++)
#pragma unroll
                for (int nt = 0; nt < 4; nt++)
                    mma_f16(acc[mt][nt],
                            af[mt][0], af[mt][1], af[mt][2], af[mt][3],
                            bf[nt >> 1][(nt & 1) * 2], bf[nt >> 1][(nt & 1) * 2 + 1]);
        }
    }

#pragma unroll
    for (int mt = 0; mt < 4; mt++) {
        const int row = by * 128 + wm * 64 + mt * 16 + grp;
#pragma unroll
        for (int nt = 0; nt < 4; nt++) {
            const int col = bx * 128 + wn * 32 + nt * 8 + 2 * q4;
            float2 bv = *(const float2*)&bias[col];
            float v0 = acc[mt][nt][0] + bv.x;
            float v1 = acc[mt][nt][1] + bv.y;
            float v2 = acc[mt][nt][2] + bv.x;
            float v3 = acc[mt][nt][3] + bv.y;
            if (OUT_HALF) {
                __half* C = (__half*)Cv;
                *(__half2*)&C[(size_t)row * N + col]       = __floats2half2_rn(v0, v1);
                *(__half2*)&C[(size_t)(row + 8) * N + col] = __floats2half2_rn(v2, v3);
            } else {
                float* C = (float*)Cv;
                float2 w0 = { v0, v1 }, w1 = { v2, v3 };
                *(float2*)&C[(size_t)row * N + col]       = w0;
                *(float2*)&C[(size_t)(row + 8) * N + col] = w1;
            }
        }
    }
}

// ---------------------------------------------------------------------------
// Flash attention v2: fp16 mma + ldmatrix + ex2.f16x2 + ones-column l-trick
// + cp.async double-buffered K/V.
// Grid (NSEQ/64, NHEAD, BATCH), 128 threads (4 warps). Warp w: query rows
// w*16..w*16+15. 64 keys/tile, 32 tiles.
// All smem tiles: 64 rows x 128 B, 16B-chunk swizzle: chunk c at c^(row&7).
//   Q [64 q][64 d]  K[2][64 k][64 d]  V[2][64 k][64 d]  P [64 q][64 k]
// Scores kept raw; softmax in base-2 with ALPHA = 0.125*log2(e) folded into
// the subtract FFMA. Row-sum l comes from a 9th PV n-tile whose B fragment
// is the constant "ones column".
// ---------------------------------------------------------------------------
#define FA_TILES (NSEQ / 64)          // 32
#define FA_SMEM  (6 * 8192)           // Q + 2K + 2V + P = 48 KB
#define ALPHA    0.1803368801111184f  // 0.125 * log2(e)

__global__ __launch_bounds__(128)
void flash_f16_kernel(const __half* __restrict__ qkv, __half* __restrict__ outp)
{
    extern __shared__ __align__(16) unsigned char fsm[];
    const uint32_t Qb = smem_u32(fsm);
    const uint32_t Kb = Qb + 8192;        // 2 buffers
    const uint32_t Vb = Kb + 2 * 8192;    // 2 buffers
    const uint32_t Pb = Vb + 2 * 8192;

    const int tid  = threadIdx.x;
    const int w    = tid >> 5;
    const int lane = tid & 31;
    const int grp  = lane >> 2;
    const int q4   = lane & 3;

    const int q0 = blockIdx.x * 64;
    const int h  = blockIdx.y;
    const int b  = blockIdx.z;

    const __half* baseQ  = qkv + (size_t)(b * NSEQ + q0) * QKV_N + h * HD;
    const __half* baseK0 = qkv + (size_t)b * NSEQ * QKV_N + DIM + h * HD;

    // K/V tile loader: 512 16B chunks each, 4 per thread per operand
    auto load_kv = [&](int tile, int buf) {
        const __half* bK = baseK0 + (size_t)(tile * 64) * QKV_N;
        const __half* bV = bK + DIM;
        const uint32_t kd = Kb + (uint32_t)buf * 8192;
        const uint32_t vd = Vb + (uint32_t)buf * 8192;
#pragma unroll
        for (int j = 0; j < 4; j++) {
            const int i   = tid + 128 * j;
            const int row = i >> 3;
            const int c   = i & 7;
            const uint32_t sw = 128u * row + 16u * (uint32_t)(c ^ (row & 7));
            cp_async16(kd + sw, bK + (size_t)row * QKV_N + c * 8);
            cp_async16(vd + sw, bV + (size_t)row * QKV_N + c * 8);
        }
        cp_commit();
    };

    // ---- group 0: Q + K0 + V0 ----
    {
#pragma unroll
        for (int j = 0; j < 4; j++) {
            const int i   = tid + 128 * j;
            const int row = i >> 3;
            const int c   = i & 7;
            cp_async16(Qb + 128u * row + 16u * (uint32_t)(c ^ (row & 7)),
                       baseQ + (size_t)row * QKV_N + c * 8);
        }
        load_kv(0, 0);   // commits Q+K0+V0 together
    }

    float m0 = -INFINITY, m1 = -INFINITY;
    float o[9][4];
#pragma unroll
    for (int t = 0; t < 9; t++)
#pragma unroll
        for (int j = 0; j < 4; j++) o[t][j] = 0.f;

    const int mrow0 = w * 16 + grp;                 // first owned S/O row
    const int arow  = w * 16 + (lane & 15);         // ldmatrix A address row
    const int ahi   = lane >> 4;
    const unsigned bone = (lane < 4) ? 0x3C003C00u : 0u;   // ones-column B frag

    for (int kt = 0; kt < FA_TILES; kt++) {
        const int cur = kt & 1;
        __syncthreads();                 // prev compute done reading buf cur^1
        if (kt + 1 < FA_TILES) { load_kv(kt + 1, cur ^ 1); cp_wait1(); }
        else                   { cp_wait0(); }
        __syncthreads();                 // tile kt resident for all warps

        const uint32_t Kcur = Kb + (uint32_t)cur * 8192;
        const uint32_t Vcur = Vb + (uint32_t)cur * 8192;

        // ---- S = Q @ K^T (raw scores) ----
        float s[8][4];
#pragma unroll
        for (int nt = 0; nt < 8; nt++)
#pragma unroll
            for (int j = 0; j < 4; j++) s[nt][j] = 0.f;

#pragma unroll
        for (int kc = 0; kc < 4; kc++) {
            unsigned a[4];
            ldsm_x4(a, Qb + 128u * arow
                        + 16u * (uint32_t)((kc * 2 + ahi) ^ (arow & 7)));
#pragma unroll
            for (int g = 0; g < 4; g++) {
                unsigned bf[4];
                const int rowb = g * 16 + (lane & 7) + ((lane & 16) ? 8 : 0);
                ldsm_x4(bf, Kcur + 128u * rowb
                             + 16u * (uint32_t)((kc * 2 + ((lane >> 3) & 1)) ^ (rowb & 7)));
                mma_f16(s[2 * g],     a[0], a[1], a[2], a[3], bf[0], bf[1]);
                mma_f16(s[2 * g + 1], a[0], a[1], a[2], a[3], bf[2], bf[3]);
            }
        }

        // ---- online softmax (base-2 domain) ----
        float mx0 = -INFINITY, mx1 = -INFINITY;
#pragma unroll
        for (int nt = 0; nt < 8; nt++) {
            mx0 = fmaxf(mx0, fmaxf(s[nt][0], s[nt][1]));
            mx1 = fmaxf(mx1, fmaxf(s[nt][2], s[nt][3]));
        }
        mx0 = fmaxf(mx0, __shfl_xor_sync(0xffffffffu, mx0, 1));
        mx0 = fmaxf(mx0, __shfl_xor_sync(0xffffffffu, mx0, 2));
        mx1 = fmaxf(mx1, __shfl_xor_sync(0xffffffffu, mx1, 1));
        mx1 = fmaxf(mx1, __shfl_xor_sync(0xffffffffu, mx1, 2));

        const float m0n = fmaxf(m0, mx0);
        const float m1n = fmaxf(m1, mx1);
        const float corr0 = exp2f(ALPHA * (m0 - m0n));
        const float corr1 = exp2f(ALPHA * (m1 - m1n));
        m0 = m0n;  m1 = m1n;
        const float na0 = -ALPHA * m0n;
        const float na1 = -ALPHA * m1n;

        const int prow1 = mrow0 + 8;
        const uint32_t pb0 = Pb + 128u * mrow0 + 4u * q4;
        const uint32_t pb1 = Pb + 128u * prow1 + 4u * q4;
#pragma unroll
        for (int nt = 0; nt < 8; nt++) {
            const float t0 = fmaf(s[nt][0], ALPHA, na0);
            const float t1 = fmaf(s[nt][1], ALPHA, na0);
            const float t2 = fmaf(s[nt][2], ALPHA, na1);
            const float t3 = fmaf(s[nt][3], ALPHA, na1);
            const unsigned p01 = ex2_f16x2(t0, t1);
            const unsigned p23 = ex2_f16x2(t2, t3);
            *(unsigned*)(size_t)0;  // (placeholder removed below)
            asm volatile("st.shared.b32 [%0], %1;"
                         :: "r"(pb0 + 16u * (uint32_t)(nt ^ (mrow0 & 7))), "r"(p01) : "memory");
            asm volatile("st.shared.b32 [%0], %1;"
                         :: "r"(pb1 + 16u * (uint32_t)(nt ^ (prow1 & 7))), "r"(p23) : "memory");
        }
#pragma unroll
        for (int t = 0; t < 9; t++) {
            o[t][0] *= corr0;  o[t][1] *= corr0;
            o[t][2] *= corr1;  o[t][3] *= corr1;
        }
        __syncwarp();

        // ---- O += P @ V  (V B-frags via ldmatrix.trans; 9th tile = ones) ----
#pragma unroll
        for (int kc = 0; kc < 4; kc++) {
            unsigned a[4];
            ldsm_x4(a, Pb + 128u * arow
                        + 16u * (uint32_t)((kc * 2 + ahi) ^ (arow & 7)));
#pragma unroll
            for (int ntp = 0; ntp < 4; ntp++) {
                unsigned bf[4];
                const int rowv = kc * 16 + (lane & 7) + ((lane & 8) ? 8 : 0);
                const int cd   = 2 * ntp + ((lane >> 4) & 1);
                ldsm_x4_t(bf, Vcur + 128u * rowv
                               + 16u * (uint32_t)(cd ^ (rowv & 7)));
                mma_f16(o[2 * ntp],     a[0], a[1], a[2], a[3], bf[0], bf[1]);
                mma_f16(o[2 * ntp + 1], a[0], a[1], a[2], a[3], bf[2], bf[3]);
            }
            mma_f16(o[8], a[0], a[1], a[2], a[3], bone, bone);
        }
        __syncwarp();
    }

    // ---- l from ones column, normalize, write fp16 ----
    const float l0v = __shfl_sync(0xffffffffu, o[8][0], lane & ~3);
    const float l1v = __shfl_sync(0xffffffffu, o[8][2], lane & ~3);
    const float inv0 = 1.f / l0v;
    const float inv1 = 1.f / l1v;

    __half* ob  = outp + (size_t)(b * NSEQ + q0 + mrow0) * DIM + h * HD;
    __half* ob1 = ob + (size_t)8 * DIM;
#pragma unroll
    for (int nt = 0; nt < 8; nt++) {
        const int col = nt * 8 + 2 * q4;
        *(__half2*)&ob[col]  = __floats2half2_rn(o[nt][0] * inv0, o[nt][1] * inv0);
        *(__half2*)&ob1[col] = __floats2half2_rn(o[nt][2] * inv1, o[nt][3] * inv1);
    }
}

// ---------------------------------------------------------------------------
// Launch
// ---------------------------------------------------------------------------
extern "C" void kernel_launch(void* const* d_in, const int* in_sizes, int n_in,
                              void* d_out, int out_size)
{
    const float* x      = (const float*)d_in[0];
    const float* w_qkv  = (const float*)d_in[1];
    const float* b_qkv  = (const float*)d_in[2];
    const float* w_proj = (const float*)d_in[3];
    const float* b_proj = (const float*)d_in[4];
    float* out = (float*)d_out;

    __half *x_h, *qkv_h, *att_h, *wqkv_h, *wproj_h;
    cudaGetSymbolAddress((void**)&x_h,     g_x_h);
    cudaGetSymbolAddress((void**)&qkv_h,   g_qkv_h);
    cudaGetSymbolAddress((void**)&att_h,   g_att_h);
    cudaGetSymbolAddress((void**)&wqkv_h,  g_wqkv_h);
    cudaGetSymbolAddress((void**)&wproj_h, g_wproj_h);

    cudaFuncSetAttribute(hgemm_kernel<true>,
                         cudaFuncAttributeMaxDynamicSharedMemorySize, GEMM_SMEM);
    cudaFuncSetAttribute(hgemm_kernel<false>,
                         cudaFuncAttributeMaxDynamicSharedMemorySize, GEMM_SMEM);
    cudaFuncSetAttribute(flash_f16_kernel,
                         cudaFuncAttributeMaxDynamicSharedMemorySize, FA_SMEM);

    // 0) precision converts + weight transposes
    {
        int n = M_ROWS * DIM;
        f32_to_f16_kernel<<<(n / 4 + 255) / 256, 256>>>(x, x_h, n);
        dim3 blk(32, 8);
        transpose_cvt_kernel<<<dim3(QKV_N / 32, DIM / 32), blk>>>(w_qkv, wqkv_h, DIM, QKV_N);
        transpose_cvt_kernel<<<dim3(DIM / 32, DIM / 32), blk>>>(w_proj, wproj_h, DIM, DIM);
    }

    // 1) QKV projection -> fp16
    {
        dim3 grid(QKV_N / 128, M_ROWS / 128);
        hgemm_kernel<true><<<grid, 256, GEMM_SMEM>>>(x_h, wqkv_h, b_qkv, qkv_h,
                                                     M_ROWS, QKV_N, DIM);
    }

    // 2) Flash attention
    {
        dim3 grid(NSEQ / 64, NHEAD, BATCH);
        flash_f16_kernel<<<grid, 128, FA_SMEM>>>(qkv_h, att_h);
    }

    // 3) Output projection -> fp32
    {
        dim3 grid(DIM / 128, M_ROWS / 128);
        hgemm_kernel<false><<<grid, 256, GEMM_SMEM>>>(att_h, wproj_h, b_proj, out,
                                                      M_ROWS, DIM, DIM);
    }
}

// round 7
// speedup vs baseline: 8.6125x; 1.0704x over previous
#include <cuda_runtime.h>
#include <cuda_fp16.h>
#include <math.h>
#include <stdint.h>

// Problem constants
#define BATCH   4
#define NSEQ    2048
#define DIM     1024
#define NHEAD   16
#define HD      64
#define M_ROWS  (BATCH * NSEQ)      // 8192
#define QKV_N   (3 * DIM)           // 3072

// ---------------------------------------------------------------------------
// Scratch (device globals: allocation-free per harness rules)
// ---------------------------------------------------------------------------
__device__ __half g_x_h[M_ROWS * DIM];       // x in fp16
__device__ __half g_qkv_h[M_ROWS * QKV_N];   // qkv in fp16
__device__ __half g_att_h[M_ROWS * DIM];     // attention out in fp16
__device__ __half g_wqkv_h[QKV_N * DIM];     // W_qkv^T  [3072,1024] fp16
__device__ __half g_wproj_h[DIM * DIM];      // W_proj^T [1024,1024] fp16

// ---------------------------------------------------------------------------
// Helpers
// ---------------------------------------------------------------------------
__device__ __forceinline__ uint32_t smem_u32(const void* p) {
    uint32_t a;
    asm("{ .reg .u64 t; cvta.to.shared.u64 t, %1; cvt.u32.u64 %0, t; }"
        : "=r"(a) : "l"(p));
    return a;
}

__device__ __forceinline__ void cp_async16(uint32_t dst, const void* src) {
    asm volatile("cp.async.cg.shared.global [%0], [%1], 16;" :: "r"(dst), "l"(src));
}
__device__ __forceinline__ void cp_commit() {
    asm volatile("cp.async.commit_group;" ::: "memory");
}
__device__ __forceinline__ void cp_wait0() {
    asm volatile("cp.async.wait_group 0;" ::: "memory");
}
__device__ __forceinline__ void cp_wait1() {
    asm volatile("cp.async.wait_group 1;" ::: "memory");
}

__device__ __forceinline__ void ldsm_x4(unsigned* r, uint32_t addr) {
    asm volatile("ldmatrix.sync.aligned.m8n8.x4.shared.b16 {%0,%1,%2,%3}, [%4];"
                 : "=r"(r[0]), "=r"(r[1]), "=r"(r[2]), "=r"(r[3]) : "r"(addr));
}
__device__ __forceinline__ void ldsm_x4_t(unsigned* r, uint32_t addr) {
    asm volatile("ldmatrix.sync.aligned.m8n8.x4.trans.shared.b16 {%0,%1,%2,%3}, [%4];"
                 : "=r"(r[0]), "=r"(r[1]), "=r"(r[2]), "=r"(r[3]) : "r"(addr));
}

// mma m16n8k16 fp16 -> fp32
__device__ __forceinline__ void mma_f16(float* c,
                                        unsigned a0, unsigned a1, unsigned a2, unsigned a3,
                                        unsigned b0, unsigned b1) {
    asm volatile(
        "mma.sync.aligned.m16n8k16.row.col.f32.f16.f16.f32 "
        "{%0,%1,%2,%3},{%4,%5,%6,%7},{%8,%9},{%0,%1,%2,%3};"
        : "+f"(c[0]), "+f"(c[1]), "+f"(c[2]), "+f"(c[3])
        : "r"(a0), "r"(a1), "r"(a2), "r"(a3), "r"(b0), "r"(b1));
}

// pack (lo, hi) f32 -> f16x2, then 2^x elementwise
__device__ __forceinline__ unsigned ex2_f16x2(float lo, float hi) {
    unsigned r;
    asm("{ .reg .b32 t; cvt.rn.f16x2.f32 t, %2, %1; ex2.approx.f16x2 %0, t; }"
        : "=r"(r) : "f"(lo), "f"(hi));
    return r;
}

// ---------------------------------------------------------------------------
// f32 -> f16 convert
// ---------------------------------------------------------------------------
__global__ void f32_to_f16_kernel(const float* __restrict__ in, __half* __restrict__ outp, int n)
{
    int i = (blockIdx.x * blockDim.x + threadIdx.x) * 4;
    if (i < n) {
        float4 v = *(const float4*)(in + i);
        *(__half2*)(outp + i)     = __floats2half2_rn(v.x, v.y);
        *(__half2*)(outp + i + 2) = __floats2half2_rn(v.z, v.w);
    }
}

// ---------------------------------------------------------------------------
// Transpose + convert: out_h[c][r] = (half) in[r][c]
// ---------------------------------------------------------------------------
__global__ void transpose_cvt_kernel(const float* __restrict__ in, __half* __restrict__ outp,
                                     int R, int C)
{
    __shared__ float t[32][33];
    const int c0 = blockIdx.x * 32;
    const int r0 = blockIdx.y * 32;
    for (int i = threadIdx.y; i < 32; i += 8)
        t[i][threadIdx.x] = in[(size_t)(r0 + i) * C + c0 + threadIdx.x];
    __syncthreads();
    for (int i = threadIdx.y; i < 32; i += 8)
        outp[(size_t)(c0 + i) * R + r0 + threadIdx.x] = __float2half(t[threadIdx.x][i]);
}

// ---------------------------------------------------------------------------
// HGEMM v2: C[M,N] = A[M,K] @ Bt^T + bias.  BK=64 halves (128 B rows),
// 128x128 tile, 256 threads (8 warps 2x4), warp tile 64x32, 3-stage cp.async.
// smem rows: 8 chunks of 16B, chunk c stored at c ^ (row & 7).
// ---------------------------------------------------------------------------
#define TS 3
#define OPB 16384                     // 128 rows * 128 B
#define STAGEB (2 * OPB)
#define GEMM_SMEM (TS * STAGEB)       // 98304

template <bool OUT_HALF>
__global__ __launch_bounds__(256, 2)
void hgemm_kernel(const __half* __restrict__ A,
                  const __half* __restrict__ Bt,
                  const float* __restrict__ bias,
                  void* __restrict__ Cv,
                  int M, int N, int K)
{
    extern __shared__ __align__(16) unsigned char dsm[];
    const uint32_t smem_base = smem_u32(dsm);

    const int tid  = threadIdx.x;
    const int warp = tid >> 5;
    const int lane = tid & 31;
    const int grp  = lane >> 2;
    const int q4   = lane & 3;

    const int wm = warp >> 2;
    const int wn = warp & 3;
    const int bx = blockIdx.x;
    const int by = blockIdx.y;

    const __half* Ag = A  + (size_t)(by * 128) * K;
    const __half* Bg = Bt + (size_t)(bx * 128) * K;
    const int NK = K / 64;

    const int rowA_base = wm * 64 + (lane & 15);
    const int hiA  = lane >> 4;
    const int rowB_base = wn * 32 + (lane & 7) + ((lane & 16) ? 8 : 0);
    const int hiB  = (lane >> 3) & 1;

    float acc[4][4][4];
#pragma unroll
    for (int mt = 0; mt < 4; mt++)
#pragma unroll
        for (int nt = 0; nt < 4; nt++)
#pragma unroll
            for (int j = 0; j < 4; j++) acc[mt][nt][j] = 0.f;

    // stage loader: 1024 16B chunks per operand, 4 per thread each
    auto load_stage = [&](int tile, int s) {
        const uint32_t base = smem_base + (uint32_t)s * STAGEB;
        const int koff = tile * 64;
#pragma unroll
        for (int j = 0; j < 4; j++) {
            const int c   = tid + 256 * j;
            const int row = c >> 3;
            const int col = c & 7;
            const uint32_t dst = base + 128u * row + 16u * (uint32_t)(col ^ (row & 7));
            cp_async16(dst,       Ag + (size_t)row * K + koff + col * 8);
            cp_async16(dst + OPB, Bg + (size_t)row * K + koff + col * 8);
        }
        cp_commit();
    };

    load_stage(0, 0);
    load_stage(1, 1);

    for (int it = 0; it < NK; it++) {
        cp_wait1();            // tile `it` resident
        __syncthreads();       // all warps done with the slot we're about to refill

        if (it + 2 < NK) load_stage(it + 2, (it + 2) % TS);
        else             cp_commit();

        const uint32_t sA = smem_base + (uint32_t)(it % TS) * STAGEB;
        const uint32_t sB = sA + OPB;

#pragma unroll
        for (int kk = 0; kk < 4; kk++) {
            unsigned af[4][4];
#pragma unroll
            for (int mt = 0; mt < 4; mt++) {
                const int r = rowA_base + mt * 16;
                ldsm_x4(af[mt], sA + 128u * r
                                   + 16u * (uint32_t)((kk * 2 + hiA) ^ (r & 7)));
            }
            unsigned bf[2][4];
#pragma unroll
            for (int ntp = 0; ntp < 2; ntp++) {
                const int r = rowB_base + ntp * 16;
                ldsm_x4(bf[ntp], sB + 128u * r
                                    + 16u * (uint32_t)((kk * 2 + hiB) ^ (r & 7)));
            }
#pragma unroll
            for (int mt = 0; mt < 4; mt++)
#pragma unroll
                for (int nt = 0; nt < 4; nt++)
                    mma_f16(acc[mt][nt],
                            af[mt][0], af[mt][1], af[mt][2], af[mt][3],
                            bf[nt >> 1][(nt & 1) * 2], bf[nt >> 1][(nt & 1) * 2 + 1]);
        }
    }

#pragma unroll
    for (int mt = 0; mt < 4; mt++) {
        const int row = by * 128 + wm * 64 + mt * 16 + grp;
#pragma unroll
        for (int nt = 0; nt < 4; nt++) {
            const int col = bx * 128 + wn * 32 + nt * 8 + 2 * q4;
            float2 bv = *(const float2*)&bias[col];
            float v0 = acc[mt][nt][0] + bv.x;
            float v1 = acc[mt][nt][1] + bv.y;
            float v2 = acc[mt][nt][2] + bv.x;
            float v3 = acc[mt][nt][3] + bv.y;
            if (OUT_HALF) {
                __half* C = (__half*)Cv;
                *(__half2*)&C[(size_t)row * N + col]       = __floats2half2_rn(v0, v1);
                *(__half2*)&C[(size_t)(row + 8) * N + col] = __floats2half2_rn(v2, v3);
            } else {
                float* C = (float*)Cv;
                float2 w0 = { v0, v1 }, w1 = { v2, v3 };
                *(float2*)&C[(size_t)row * N + col]       = w0;
                *(float2*)&C[(size_t)(row + 8) * N + col] = w1;
            }
        }
    }
}

// ---------------------------------------------------------------------------
// Flash attention v3: fp16 mma, P kept entirely in registers (S C-fragment
// == PV A-fragment identity), Q fragments hoisted out of the key loop,
// ex2.f16x2 softmax, ones-column row-sum, cp.async double-buffered K/V.
// Grid (NSEQ/64, NHEAD, BATCH), 128 threads (4 warps).
//   smem: Q [64][64]  K[2][64][64]  V[2][64][64]  (all half, 128B swizzled rows)
// ---------------------------------------------------------------------------
#define FA_TILES (NSEQ / 64)          // 32
#define FA_SMEM  (5 * 8192)           // Q + 2K + 2V = 40 KB
#define ALPHA    0.1803368801111184f  // 0.125 * log2(e)

__global__ __launch_bounds__(128)
void flash_f16_kernel(const __half* __restrict__ qkv, __half* __restrict__ outp)
{
    extern __shared__ __align__(16) unsigned char fsm[];
    const uint32_t Qb = smem_u32(fsm);
    const uint32_t Kb = Qb + 8192;        // 2 buffers
    const uint32_t Vb = Kb + 2 * 8192;    // 2 buffers

    const int tid  = threadIdx.x;
    const int w    = tid >> 5;
    const int lane = tid & 31;
    const int grp  = lane >> 2;
    const int q4   = lane & 3;

    const int q0 = blockIdx.x * 64;
    const int h  = blockIdx.y;
    const int b  = blockIdx.z;

    const __half* baseQ  = qkv + (size_t)(b * NSEQ + q0) * QKV_N + h * HD;
    const __half* baseK0 = qkv + (size_t)b * NSEQ * QKV_N + DIM + h * HD;

    auto load_kv = [&](int tile, int buf) {
        const __half* bK = baseK0 + (size_t)(tile * 64) * QKV_N;
        const __half* bV = bK + DIM;
        const uint32_t kd = Kb + (uint32_t)buf * 8192;
        const uint32_t vd = Vb + (uint32_t)buf * 8192;
#pragma unroll
        for (int j = 0; j < 4; j++) {
            const int i   = tid + 128 * j;
            const int row = i >> 3;
            const int c   = i & 7;
            const uint32_t sw = 128u * row + 16u * (uint32_t)(c ^ (row & 7));
            cp_async16(kd + sw, bK + (size_t)row * QKV_N + c * 8);
            cp_async16(vd + sw, bV + (size_t)row * QKV_N + c * 8);
        }
        cp_commit();
    };

    // prologue: Q + K0 + V0 in one group
    {
#pragma unroll
        for (int j = 0; j < 4; j++) {
            const int i   = tid + 128 * j;
            const int row = i >> 3;
            const int c   = i & 7;
            cp_async16(Qb + 128u * row + 16u * (uint32_t)(c ^ (row & 7)),
                       baseQ + (size_t)row * QKV_N + c * 8);
        }
        load_kv(0, 0);
    }

    float m0 = -INFINITY, m1 = -INFINITY;
    float o[9][4];
#pragma unroll
    for (int t = 0; t < 9; t++)
#pragma unroll
        for (int j = 0; j < 4; j++) o[t][j] = 0.f;

    const int mrow0 = w * 16 + grp;                 // first owned S/O row
    const int arow  = w * 16 + (lane & 15);         // ldmatrix A address row
    const int ahi   = lane >> 4;
    const unsigned bone = (lane < 4) ? 0x3C003C00u : 0u;   // ones-column B frag

    unsigned qa[4][4];   // hoisted Q A-fragments (one per 16-wide d chunk)

    for (int kt = 0; kt < FA_TILES; kt++) {
        const int cur = kt & 1;
        __syncthreads();                 // prev compute done reading buf cur^1
        if (kt + 1 < FA_TILES) { load_kv(kt + 1, cur ^ 1); cp_wait1(); }
        else                   { cp_wait0(); }
        __syncthreads();                 // tile kt resident for all warps

        if (kt == 0) {
#pragma unroll
            for (int kc = 0; kc < 4; kc++)
                ldsm_x4(qa[kc], Qb + 128u * arow
                               + 16u * (uint32_t)((kc * 2 + ahi) ^ (arow & 7)));
        }

        const uint32_t Kcur = Kb + (uint32_t)cur * 8192;
        const uint32_t Vcur = Vb + (uint32_t)cur * 8192;

        // ---- S = Q @ K^T (raw scores) ----
        float s[8][4];
#pragma unroll
        for (int nt = 0; nt < 8; nt++)
#pragma unroll
            for (int j = 0; j < 4; j++) s[nt][j] = 0.f;

#pragma unroll
        for (int kc = 0; kc < 4; kc++) {
#pragma unroll
            for (int g = 0; g < 4; g++) {
                unsigned bf[4];
                const int rowb = g * 16 + (lane & 7) + ((lane & 16) ? 8 : 0);
                ldsm_x4(bf, Kcur + 128u * rowb
                             + 16u * (uint32_t)((kc * 2 + ((lane >> 3) & 1)) ^ (rowb & 7)));
                mma_f16(s[2 * g],     qa[kc][0], qa[kc][1], qa[kc][2], qa[kc][3], bf[0], bf[1]);
                mma_f16(s[2 * g + 1], qa[kc][0], qa[kc][1], qa[kc][2], qa[kc][3], bf[2], bf[3]);
            }
        }

        // ---- online softmax (base-2); P -> registers only ----
        float mx0 = -INFINITY, mx1 = -INFINITY;
#pragma unroll
        for (int nt = 0; nt < 8; nt++) {
            mx0 = fmaxf(mx0, fmaxf(s[nt][0], s[nt][1]));
            mx1 = fmaxf(mx1, fmaxf(s[nt][2], s[nt][3]));
        }
        mx0 = fmaxf(mx0, __shfl_xor_sync(0xffffffffu, mx0, 1));
        mx0 = fmaxf(mx0, __shfl_xor_sync(0xffffffffu, mx0, 2));
        mx1 = fmaxf(mx1, __shfl_xor_sync(0xffffffffu, mx1, 1));
        mx1 = fmaxf(mx1, __shfl_xor_sync(0xffffffffu, mx1, 2));

        const float m0n = fmaxf(m0, mx0);
        const float m1n = fmaxf(m1, mx1);
        const float corr0 = exp2f(ALPHA * (m0 - m0n));
        const float corr1 = exp2f(ALPHA * (m1 - m1n));
        m0 = m0n;  m1 = m1n;
        const float na0 = -ALPHA * m0n;
        const float na1 = -ALPHA * m1n;

        unsigned p01[8], p23[8];
#pragma unroll
        for (int nt = 0; nt < 8; nt++) {
            p01[nt] = ex2_f16x2(fmaf(s[nt][0], ALPHA, na0), fmaf(s[nt][1], ALPHA, na0));
            p23[nt] = ex2_f16x2(fmaf(s[nt][2], ALPHA, na1), fmaf(s[nt][3], ALPHA, na1));
        }
#pragma unroll
        for (int t = 0; t < 9; t++) {
            o[t][0] *= corr0;  o[t][1] *= corr0;
            o[t][2] *= corr1;  o[t][3] *= corr1;
        }

        // ---- O += P @ V  (P A-frags direct from registers; ones = l) ----
#pragma unroll
        for (int kc = 0; kc < 4; kc++) {
            const unsigned a0 = p01[2 * kc];
            const unsigned a1 = p23[2 * kc];
            const unsigned a2 = p01[2 * kc + 1];
            const unsigned a3 = p23[2 * kc + 1];
#pragma unroll
            for (int ntp = 0; ntp < 4; ntp++) {
                unsigned bf[4];
                const int rowv = kc * 16 + (lane & 7) + ((lane & 8) ? 8 : 0);
                const int cd   = 2 * ntp + ((lane >> 4) & 1);
                ldsm_x4_t(bf, Vcur + 128u * rowv
                               + 16u * (uint32_t)(cd ^ (rowv & 7)));
                mma_f16(o[2 * ntp],     a0, a1, a2, a3, bf[0], bf[1]);
                mma_f16(o[2 * ntp + 1], a0, a1, a2, a3, bf[2], bf[3]);
            }
            mma_f16(o[8], a0, a1, a2, a3, bone, bone);
        }
    }

    // ---- l from ones column, normalize, write fp16 ----
    const float l0v = __shfl_sync(0xffffffffu, o[8][0], lane & ~3);
    const float l1v = __shfl_sync(0xffffffffu, o[8][2], lane & ~3);
    const float inv0 = 1.f / l0v;
    const float inv1 = 1.f / l1v;

    __half* ob  = outp + (size_t)(b * NSEQ + q0 + mrow0) * DIM + h * HD;
    __half* ob1 = ob + (size_t)8 * DIM;
#pragma unroll
    for (int nt = 0; nt < 8; nt++) {
        const int col = nt * 8 + 2 * q4;
        *(__half2*)&ob[col]  = __floats2half2_rn(o[nt][0] * inv0, o[nt][1] * inv0);
        *(__half2*)&ob1[col] = __floats2half2_rn(o[nt][2] * inv1, o[nt][3] * inv1);
    }
}

// ---------------------------------------------------------------------------
// Launch
// ---------------------------------------------------------------------------
extern "C" void kernel_launch(void* const* d_in, const int* in_sizes, int n_in,
                              void* d_out, int out_size)
{
    const float* x      = (const float*)d_in[0];
    const float* w_qkv  = (const float*)d_in[1];
    const float* b_qkv  = (const float*)d_in[2];
    const float* w_proj = (const float*)d_in[3];
    const float* b_proj = (const float*)d_in[4];
    float* out = (float*)d_out;

    __half *x_h, *qkv_h, *att_h, *wqkv_h, *wproj_h;
    cudaGetSymbolAddress((void**)&x_h,     g_x_h);
    cudaGetSymbolAddress((void**)&qkv_h,   g_qkv_h);
    cudaGetSymbolAddress((void**)&att_h,   g_att_h);
    cudaGetSymbolAddress((void**)&wqkv_h,  g_wqkv_h);
    cudaGetSymbolAddress((void**)&wproj_h, g_wproj_h);

    cudaFuncSetAttribute(hgemm_kernel<true>,
                         cudaFuncAttributeMaxDynamicSharedMemorySize, GEMM_SMEM);
    cudaFuncSetAttribute(hgemm_kernel<false>,
                         cudaFuncAttributeMaxDynamicSharedMemorySize, GEMM_SMEM);
    cudaFuncSetAttribute(flash_f16_kernel,
                         cudaFuncAttributeMaxDynamicSharedMemorySize, FA_SMEM);

    // 0) precision converts + weight transposes
    {
        int n = M_ROWS * DIM;
        f32_to_f16_kernel<<<(n / 4 + 255) / 256, 256>>>(x, x_h, n);
        dim3 blk(32, 8);
        transpose_cvt_kernel<<<dim3(QKV_N / 32, DIM / 32), blk>>>(w_qkv, wqkv_h, DIM, QKV_N);
        transpose_cvt_kernel<<<dim3(DIM / 32, DIM / 32), blk>>>(w_proj, wproj_h, DIM, DIM);
    }

    // 1) QKV projection -> fp16
    {
        dim3 grid(QKV_N / 128, M_ROWS / 128);
        hgemm_kernel<true><<<grid, 256, GEMM_SMEM>>>(x_h, wqkv_h, b_qkv, qkv_h,
                                                     M_ROWS, QKV_N, DIM);
    }

    // 2) Flash attention
    {
        dim3 grid(NSEQ / 64, NHEAD, BATCH);
        flash_f16_kernel<<<grid, 128, FA_SMEM>>>(qkv_h, att_h);
    }

    // 3) Output projection -> fp32
    {
        dim3 grid(DIM / 128, M_ROWS / 128);
        hgemm_kernel<false><<<grid, 256, GEMM_SMEM>>>(att_h, wproj_h, b_proj, out,
                                                      M_ROWS, DIM, DIM);
    }
}

// round 8
// speedup vs baseline: 8.6450x; 1.0038x over previous
#include <cuda_runtime.h>
#include <cuda_fp16.h>
#include <math.h>
#include <stdint.h>

// Problem constants
#define BATCH   4
#define NSEQ    2048
#define DIM     1024
#define NHEAD   16
#define HD      64
#define M_ROWS  (BATCH * NSEQ)      // 8192
#define QKV_N   (3 * DIM)           // 3072

// ---------------------------------------------------------------------------
// Scratch (device globals: allocation-free per harness rules)
// ---------------------------------------------------------------------------
__device__ __half g_x_h[M_ROWS * DIM];       // x in fp16
__device__ __half g_qkv_h[M_ROWS * QKV_N];   // qkv in fp16
__device__ __half g_att_h[M_ROWS * DIM];     // attention out in fp16
__device__ __half g_wqkv_h[QKV_N * DIM];     // W_qkv^T  [3072,1024] fp16
__device__ __half g_wproj_h[DIM * DIM];      // W_proj^T [1024,1024] fp16

// ---------------------------------------------------------------------------
// Helpers
// ---------------------------------------------------------------------------
__device__ __forceinline__ uint32_t smem_u32(const void* p) {
    uint32_t a;
    asm("{ .reg .u64 t; cvta.to.shared.u64 t, %1; cvt.u32.u64 %0, t; }"
        : "=r"(a) : "l"(p));
    return a;
}

__device__ __forceinline__ void cp_async16(uint32_t dst, const void* src) {
    asm volatile("cp.async.cg.shared.global [%0], [%1], 16;" :: "r"(dst), "l"(src));
}
__device__ __forceinline__ void cp_commit() {
    asm volatile("cp.async.commit_group;" ::: "memory");
}
__device__ __forceinline__ void cp_wait0() {
    asm volatile("cp.async.wait_group 0;" ::: "memory");
}
__device__ __forceinline__ void cp_wait1() {
    asm volatile("cp.async.wait_group 1;" ::: "memory");
}

__device__ __forceinline__ void ldsm_x4(unsigned* r, uint32_t addr) {
    asm volatile("ldmatrix.sync.aligned.m8n8.x4.shared.b16 {%0,%1,%2,%3}, [%4];"
                 : "=r"(r[0]), "=r"(r[1]), "=r"(r[2]), "=r"(r[3]) : "r"(addr));
}
__device__ __forceinline__ void ldsm_x4_t(unsigned* r, uint32_t addr) {
    asm volatile("ldmatrix.sync.aligned.m8n8.x4.trans.shared.b16 {%0,%1,%2,%3}, [%4];"
                 : "=r"(r[0]), "=r"(r[1]), "=r"(r[2]), "=r"(r[3]) : "r"(addr));
}

// mma m16n8k16 fp16 -> fp32
__device__ __forceinline__ void mma_f16(float* c,
                                        unsigned a0, unsigned a1, unsigned a2, unsigned a3,
                                        unsigned b0, unsigned b1) {
    asm volatile(
        "mma.sync.aligned.m16n8k16.row.col.f32.f16.f16.f32 "
        "{%0,%1,%2,%3},{%4,%5,%6,%7},{%8,%9},{%0,%1,%2,%3};"
        : "+f"(c[0]), "+f"(c[1]), "+f"(c[2]), "+f"(c[3])
        : "r"(a0), "r"(a1), "r"(a2), "r"(a3), "r"(b0), "r"(b1));
}

// pack (lo, hi) f32 -> f16x2, then 2^x elementwise
__device__ __forceinline__ unsigned ex2_f16x2(float lo, float hi) {
    unsigned r;
    asm("{ .reg .b32 t; cvt.rn.f16x2.f32 t, %2, %1; ex2.approx.f16x2 %0, t; }"
        : "=r"(r) : "f"(lo), "f"(hi));
    return r;
}

// ---------------------------------------------------------------------------
// f32 -> f16 convert
// ---------------------------------------------------------------------------
__global__ void f32_to_f16_kernel(const float* __restrict__ in, __half* __restrict__ outp, int n)
{
    int i = (blockIdx.x * blockDim.x + threadIdx.x) * 4;
    if (i < n) {
        float4 v = *(const float4*)(in + i);
        *(__half2*)(outp + i)     = __floats2half2_rn(v.x, v.y);
        *(__half2*)(outp + i + 2) = __floats2half2_rn(v.z, v.w);
    }
}

// ---------------------------------------------------------------------------
// Transpose + convert: out_h[c][r] = (half) in[r][c]
// ---------------------------------------------------------------------------
__global__ void transpose_cvt_kernel(const float* __restrict__ in, __half* __restrict__ outp,
                                     int R, int C)
{
    __shared__ float t[32][33];
    const int c0 = blockIdx.x * 32;
    const int r0 = blockIdx.y * 32;
    for (int i = threadIdx.y; i < 32; i += 8)
        t[i][threadIdx.x] = in[(size_t)(r0 + i) * C + c0 + threadIdx.x];
    __syncthreads();
    for (int i = threadIdx.y; i < 32; i += 8)
        outp[(size_t)(c0 + i) * R + r0 + threadIdx.x] = __float2half(t[threadIdx.x][i]);
}

// ---------------------------------------------------------------------------
// HGEMM v2: C[M,N] = A[M,K] @ Bt^T + bias.  BK=64 halves (128 B rows),
// 128x128 tile, 256 threads (8 warps 2x4), warp tile 64x32, 3-stage cp.async.
// smem rows: 8 chunks of 16B, chunk c stored at c ^ (row & 7).
// ---------------------------------------------------------------------------
#define TS 3
#define OPB 16384                     // 128 rows * 128 B
#define STAGEB (2 * OPB)
#define GEMM_SMEM (TS * STAGEB)       // 98304

template <bool OUT_HALF>
__global__ __launch_bounds__(256, 2)
void hgemm_kernel(const __half* __restrict__ A,
                  const __half* __restrict__ Bt,
                  const float* __restrict__ bias,
                  void* __restrict__ Cv,
                  int M, int N, int K)
{
    extern __shared__ __align__(16) unsigned char dsm[];
    const uint32_t smem_base = smem_u32(dsm);

    const int tid  = threadIdx.x;
    const int warp = tid >> 5;
    const int lane = tid & 31;
    const int grp  = lane >> 2;
    const int q4   = lane & 3;

    const int wm = warp >> 2;
    const int wn = warp & 3;
    const int bx = blockIdx.x;
    const int by = blockIdx.y;

    const __half* Ag = A  + (size_t)(by * 128) * K;
    const __half* Bg = Bt + (size_t)(bx * 128) * K;
    const int NK = K / 64;

    const int rowA_base = wm * 64 + (lane & 15);
    const int hiA  = lane >> 4;
    const int rowB_base = wn * 32 + (lane & 7) + ((lane & 16) ? 8 : 0);
    const int hiB  = (lane >> 3) & 1;

    float acc[4][4][4];
#pragma unroll
    for (int mt = 0; mt < 4; mt++)
#pragma unroll
        for (int nt = 0; nt < 4; nt++)
#pragma unroll
            for (int j = 0; j < 4; j++) acc[mt][nt][j] = 0.f;

    // stage loader: 1024 16B chunks per operand, 4 per thread each
    auto load_stage = [&](int tile, int s) {
        const uint32_t base = smem_base + (uint32_t)s * STAGEB;
        const int koff = tile * 64;
#pragma unroll
        for (int j = 0; j < 4; j++) {
            const int c   = tid + 256 * j;
            const int row = c >> 3;
            const int col = c & 7;
            const uint32_t dst = base + 128u * row + 16u * (uint32_t)(col ^ (row & 7));
            cp_async16(dst,       Ag + (size_t)row * K + koff + col * 8);
            cp_async16(dst + OPB, Bg + (size_t)row * K + koff + col * 8);
        }
        cp_commit();
    };

    load_stage(0, 0);
    load_stage(1, 1);

    for (int it = 0; it < NK; it++) {
        cp_wait1();            // tile `it` resident
        __syncthreads();       // all warps done with the slot we're about to refill

        if (it + 2 < NK) load_stage(it + 2, (it + 2) % TS);
        else             cp_commit();

        const uint32_t sA = smem_base + (uint32_t)(it % TS) * STAGEB;
        const uint32_t sB = sA + OPB;

#pragma unroll
        for (int kk = 0; kk < 4; kk++) {
            unsigned af[4][4];
#pragma unroll
            for (int mt = 0; mt < 4; mt++) {
                const int r = rowA_base + mt * 16;
                ldsm_x4(af[mt], sA + 128u * r
                                   + 16u * (uint32_t)((kk * 2 + hiA) ^ (r & 7)));
            }
            unsigned bf[2][4];
#pragma unroll
            for (int ntp = 0; ntp < 2; ntp++) {
                const int r = rowB_base + ntp * 16;
                ldsm_x4(bf[ntp], sB + 128u * r
                                    + 16u * (uint32_t)((kk * 2 + hiB) ^ (r & 7)));
            }
#pragma unroll
            for (int mt = 0; mt < 4; mt++)
#pragma unroll
                for (int nt = 0; nt < 4; nt++)
                    mma_f16(acc[mt][nt],
                            af[mt][0], af[mt][1], af[mt][2], af[mt][3],
                            bf[nt >> 1][(nt & 1) * 2], bf[nt >> 1][(nt & 1) * 2 + 1]);
        }
    }

#pragma unroll
    for (int mt = 0; mt < 4; mt++) {
        const int row = by * 128 + wm * 64 + mt * 16 + grp;
#pragma unroll
        for (int nt = 0; nt < 4; nt++) {
            const int col = bx * 128 + wn * 32 + nt * 8 + 2 * q4;
            float2 bv = *(const float2*)&bias[col];
            float v0 = acc[mt][nt][0] + bv.x;
            float v1 = acc[mt][nt][1] + bv.y;
            float v2 = acc[mt][nt][2] + bv.x;
            float v3 = acc[mt][nt][3] + bv.y;
            if (OUT_HALF) {
                __half* C = (__half*)Cv;
                *(__half2*)&C[(size_t)row * N + col]       = __floats2half2_rn(v0, v1);
                *(__half2*)&C[(size_t)(row + 8) * N + col] = __floats2half2_rn(v2, v3);
            } else {
                float* C = (float*)Cv;
                float2 w0 = { v0, v1 }, w1 = { v2, v3 };
                *(float2*)&C[(size_t)row * N + col]       = w0;
                *(float2*)&C[(size_t)(row + 8) * N + col] = w1;
            }
        }
    }
}

// ---------------------------------------------------------------------------
// Flash attention v3: fp16 mma, P kept entirely in registers (S C-fragment
// == PV A-fragment identity), Q fragments hoisted out of the key loop,
// ex2.f16x2 softmax, ones-column row-sum, cp.async double-buffered K/V.
// Grid (NSEQ/64, NHEAD, BATCH), 128 threads (4 warps).
//   smem: Q [64][64]  K[2][64][64]  V[2][64][64]  (all half, 128B swizzled rows)
// ---------------------------------------------------------------------------
#define FA_TILES (NSEQ / 64)          // 32
#define FA_SMEM  (5 * 8192)           // Q + 2K + 2V = 40 KB
#define ALPHA    0.1803368801111184f  // 0.125 * log2(e)

__global__ __launch_bounds__(128)
void flash_f16_kernel(const __half* __restrict__ qkv, __half* __restrict__ outp)
{
    extern __shared__ __align__(16) unsigned char fsm[];
    const uint32_t Qb = smem_u32(fsm);
    const uint32_t Kb = Qb + 8192;        // 2 buffers
    const uint32_t Vb = Kb + 2 * 8192;    // 2 buffers

    const int tid  = threadIdx.x;
    const int w    = tid >> 5;
    const int lane = tid & 31;
    const int grp  = lane >> 2;
    const int q4   = lane & 3;

    const int q0 = blockIdx.x * 64;
    const int h  = blockIdx.y;
    const int b  = blockIdx.z;

    const __half* baseQ  = qkv + (size_t)(b * NSEQ + q0) * QKV_N + h * HD;
    const __half* baseK0 = qkv + (size_t)b * NSEQ * QKV_N + DIM + h * HD;

    auto load_kv = [&](int tile, int buf) {
        const __half* bK = baseK0 + (size_t)(tile * 64) * QKV_N;
        const __half* bV = bK + DIM;
        const uint32_t kd = Kb + (uint32_t)buf * 8192;
        const uint32_t vd = Vb + (uint32_t)buf * 8192;
#pragma unroll
        for (int j = 0; j < 4; j++) {
            const int i   = tid + 128 * j;
            const int row = i >> 3;
            const int c   = i & 7;
            const uint32_t sw = 128u * row + 16u * (uint32_t)(c ^ (row & 7));
            cp_async16(kd + sw, bK + (size_t)row * QKV_N + c * 8);
            cp_async16(vd + sw, bV + (size_t)row * QKV_N + c * 8);
        }
        cp_commit();
    };

    // prologue: Q + K0 + V0 in one group
    {
#pragma unroll
        for (int j = 0; j < 4; j++) {
            const int i   = tid + 128 * j;
            const int row = i >> 3;
            const int c   = i & 7;
            cp_async16(Qb + 128u * row + 16u * (uint32_t)(c ^ (row & 7)),
                       baseQ + (size_t)row * QKV_N + c * 8);
        }
        load_kv(0, 0);
    }

    float m0 = -INFINITY, m1 = -INFINITY;
    float o[9][4];
#pragma unroll
    for (int t = 0; t < 9; t++)
#pragma unroll
        for (int j = 0; j < 4; j++) o[t][j] = 0.f;

    const int mrow0 = w * 16 + grp;                 // first owned S/O row
    const int arow  = w * 16 + (lane & 15);         // ldmatrix A address row
    const int ahi   = lane >> 4;
    const unsigned bone = (lane < 4) ? 0x3C003C00u : 0u;   // ones-column B frag

    unsigned qa[4][4];   // hoisted Q A-fragments (one per 16-wide d chunk)

    for (int kt = 0; kt < FA_TILES; kt++) {
        const int cur = kt & 1;
        __syncthreads();                 // prev compute done reading buf cur^1
        if (kt + 1 < FA_TILES) { load_kv(kt + 1, cur ^ 1); cp_wait1(); }
        else                   { cp_wait0(); }
        __syncthreads();                 // tile kt resident for all warps

        if (kt == 0) {
#pragma unroll
            for (int kc = 0; kc < 4; kc++)
                ldsm_x4(qa[kc], Qb + 128u * arow
                               + 16u * (uint32_t)((kc * 2 + ahi) ^ (arow & 7)));
        }

        const uint32_t Kcur = Kb + (uint32_t)cur * 8192;
        const uint32_t Vcur = Vb + (uint32_t)cur * 8192;

        // ---- S = Q @ K^T (raw scores) ----
        float s[8][4];
#pragma unroll
        for (int nt = 0; nt < 8; nt++)
#pragma unroll
            for (int j = 0; j < 4; j++) s[nt][j] = 0.f;

#pragma unroll
        for (int kc = 0; kc < 4; kc++) {
#pragma unroll
            for (int g = 0; g < 4; g++) {
                unsigned bf[4];
                const int rowb = g * 16 + (lane & 7) + ((lane & 16) ? 8 : 0);
                ldsm_x4(bf, Kcur + 128u * rowb
                             + 16u * (uint32_t)((kc * 2 + ((lane >> 3) & 1)) ^ (rowb & 7)));
                mma_f16(s[2 * g],     qa[kc][0], qa[kc][1], qa[kc][2], qa[kc][3], bf[0], bf[1]);
                mma_f16(s[2 * g + 1], qa[kc][0], qa[kc][1], qa[kc][2], qa[kc][3], bf[2], bf[3]);
            }
        }

        // ---- online softmax (base-2); P -> registers only ----
        float mx0 = -INFINITY, mx1 = -INFINITY;
#pragma unroll
        for (int nt = 0; nt < 8; nt++) {
            mx0 = fmaxf(mx0, fmaxf(s[nt][0], s[nt][1]));
            mx1 = fmaxf(mx1, fmaxf(s[nt][2], s[nt][3]));
        }
        mx0 = fmaxf(mx0, __shfl_xor_sync(0xffffffffu, mx0, 1));
        mx0 = fmaxf(mx0, __shfl_xor_sync(0xffffffffu, mx0, 2));
        mx1 = fmaxf(mx1, __shfl_xor_sync(0xffffffffu, mx1, 1));
        mx1 = fmaxf(mx1, __shfl_xor_sync(0xffffffffu, mx1, 2));

        const float m0n = fmaxf(m0, mx0);
        const float m1n = fmaxf(m1, mx1);
        const float corr0 = exp2f(ALPHA * (m0 - m0n));
        const float corr1 = exp2f(ALPHA * (m1 - m1n));
        m0 = m0n;  m1 = m1n;
        const float na0 = -ALPHA * m0n;
        const float na1 = -ALPHA * m1n;

        unsigned p01[8], p23[8];
#pragma unroll
        for (int nt = 0; nt < 8; nt++) {
            p01[nt] = ex2_f16x2(fmaf(s[nt][0], ALPHA, na0), fmaf(s[nt][1], ALPHA, na0));
            p23[nt] = ex2_f16x2(fmaf(s[nt][2], ALPHA, na1), fmaf(s[nt][3], ALPHA, na1));
        }
#pragma unroll
        for (int t = 0; t < 9; t++) {
            o[t][0] *= corr0;  o[t][1] *= corr0;
            o[t][2] *= corr1;  o[t][3] *= corr1;
        }

        // ---- O += P @ V  (P A-frags direct from registers; ones = l) ----
#pragma unroll
        for (int kc = 0; kc < 4; kc++) {
            const unsigned a0 = p01[2 * kc];
            const unsigned a1 = p23[2 * kc];
            const unsigned a2 = p01[2 * kc + 1];
            const unsigned a3 = p23[2 * kc + 1];
#pragma unroll
            for (int ntp = 0; ntp < 4; ntp++) {
                unsigned bf[4];
                const int rowv = kc * 16 + (lane & 7) + ((lane & 8) ? 8 : 0);
                const int cd   = 2 * ntp + ((lane >> 4) & 1);
                ldsm_x4_t(bf, Vcur + 128u * rowv
                               + 16u * (uint32_t)(cd ^ (rowv & 7)));
                mma_f16(o[2 * ntp],     a0, a1, a2, a3, bf[0], bf[1]);
                mma_f16(o[2 * ntp + 1], a0, a1, a2, a3, bf[2], bf[3]);
            }
            mma_f16(o[8], a0, a1, a2, a3, bone, bone);
        }
    }

    // ---- l from ones column, normalize, write fp16 ----
    const float l0v = __shfl_sync(0xffffffffu, o[8][0], lane & ~3);
    const float l1v = __shfl_sync(0xffffffffu, o[8][2], lane & ~3);
    const float inv0 = 1.f / l0v;
    const float inv1 = 1.f / l1v;

    __half* ob  = outp + (size_t)(b * NSEQ + q0 + mrow0) * DIM + h * HD;
    __half* ob1 = ob + (size_t)8 * DIM;
#pragma unroll
    for (int nt = 0; nt < 8; nt++) {
        const int col = nt * 8 + 2 * q4;
        *(__half2*)&ob[col]  = __floats2half2_rn(o[nt][0] * inv0, o[nt][1] * inv0);
        *(__half2*)&ob1[col] = __floats2half2_rn(o[nt][2] * inv1, o[nt][3] * inv1);
    }
}

// ---------------------------------------------------------------------------
// Launch
// ---------------------------------------------------------------------------
extern "C" void kernel_launch(void* const* d_in, const int* in_sizes, int n_in,
                              void* d_out, int out_size)
{
    const float* x      = (const float*)d_in[0];
    const float* w_qkv  = (const float*)d_in[1];
    const float* b_qkv  = (const float*)d_in[2];
    const float* w_proj = (const float*)d_in[3];
    const float* b_proj = (const float*)d_in[4];
    float* out = (float*)d_out;

    __half *x_h, *qkv_h, *att_h, *wqkv_h, *wproj_h;
    cudaGetSymbolAddress((void**)&x_h,     g_x_h);
    cudaGetSymbolAddress((void**)&qkv_h,   g_qkv_h);
    cudaGetSymbolAddress((void**)&att_h,   g_att_h);
    cudaGetSymbolAddress((void**)&wqkv_h,  g_wqkv_h);
    cudaGetSymbolAddress((void**)&wproj_h, g_wproj_h);

    cudaFuncSetAttribute(hgemm_kernel<true>,
                         cudaFuncAttributeMaxDynamicSharedMemorySize, GEMM_SMEM);
    cudaFuncSetAttribute(hgemm_kernel<false>,
                         cudaFuncAttributeMaxDynamicSharedMemorySize, GEMM_SMEM);
    cudaFuncSetAttribute(flash_f16_kernel,
                         cudaFuncAttributeMaxDynamicSharedMemorySize, FA_SMEM);

    // 0) precision converts + weight transposes
    {
        int n = M_ROWS * DIM;
        f32_to_f16_kernel<<<(n / 4 + 255) / 256, 256>>>(x, x_h, n);
        dim3 blk(32, 8);
        transpose_cvt_kernel<<<dim3(QKV_N / 32, DIM / 32), blk>>>(w_qkv, wqkv_h, DIM, QKV_N);
        transpose_cvt_kernel<<<dim3(DIM / 32, DIM / 32), blk>>>(w_proj, wproj_h, DIM, DIM);
    }

    // 1) QKV projection -> fp16
    {
        dim3 grid(QKV_N / 128, M_ROWS / 128);
        hgemm_kernel<true><<<grid, 256, GEMM_SMEM>>>(x_h, wqkv_h, b_qkv, qkv_h,
                                                     M_ROWS, QKV_N, DIM);
    }

    // 2) Flash attention
    {
        dim3 grid(NSEQ / 64, NHEAD, BATCH);
        flash_f16_kernel<<<grid, 128, FA_SMEM>>>(qkv_h, att_h);
    }

    // 3) Output projection -> fp32
    {
        dim3 grid(DIM / 128, M_ROWS / 128);
        hgemm_kernel<false><<<grid, 256, GEMM_SMEM>>>(att_h, wproj_h, b_proj, out,
                                                      M_ROWS, DIM, DIM);
    }
}